// round 8
// baseline (speedup 1.0000x reference)
#include <cuda_runtime.h>
#include <math.h>

// ---- problem constants ----
#define F      128
#define F3     384
#define NRBF   20
#define NATOMS 8000
#define NEDGES 160000
#define NMOLS  100
#define NCONV  3
#define CUTOFF 5.0f

#define TA  8    // atoms per half in phi/upd kernels (16 per block)
#define TAM 4    // atoms per block in msg kernel
#define CAP 64   // max active edges per destination atom

// ---- device scratch ----
__device__ float g_s   [NATOMS * F];
__device__ float g_v   [NATOMS * F3];
__device__ float g_ds  [NATOMS * F];
__device__ float g_dv  [NATOMS * F3];
__device__ float g_phi [NATOMS * F3];
__device__ float g_rbf [NEDGES * NRBF];   // env-premultiplied
__device__ float g_env [NEDGES];
__device__ float g_unit[NEDGES * 3];
__device__ int   g_cnt [NATOMS];
__device__ int   g_list[NATOMS * CAP];

__device__ __forceinline__ float silu(float x) { return x / (1.0f + __expf(-x)); }

// packed fp32x2 helpers
#define FFMA2(acc, a, b) asm("fma.rn.f32x2 %0, %1, %2, %0;" : "+l"(acc) : "l"(a), "l"(b))
__device__ __forceinline__ unsigned long long pk2(float x, float y) {
    unsigned long long r; asm("mov.b64 %0, {%1, %2};" : "=l"(r) : "f"(x), "f"(y)); return r;
}
__device__ __forceinline__ float2 upk2(unsigned long long v) {
    float2 o; asm("mov.b64 {%0, %1}, %2;" : "=f"(o.x), "=f"(o.y) : "l"(v)); return o;
}

// ---------------------------------------------------------------------------
// init
// ---------------------------------------------------------------------------
__global__ void k_init(const float* __restrict__ emb, const int* __restrict__ z)
{
    int a = blockIdx.x, f = threadIdx.x;
    g_s[a * F + f] = emb[z[a] * F + f];
    int b = a * F3 + f * 3;
    g_v[b] = 0.0f; g_v[b + 1] = 0.0f; g_v[b + 2] = 0.0f;
    if (f == 0) g_cnt[a] = 0;
}

// ---------------------------------------------------------------------------
// edge geometry + CSR build
// ---------------------------------------------------------------------------
__global__ void k_edges(const float* __restrict__ xyz, const int* __restrict__ nbrs, int E)
{
    int e = blockIdx.x * 256 + threadIdx.x;
    if (e >= E) return;
    int i = nbrs[2 * e], j = nbrs[2 * e + 1];
    float rx = xyz[3 * j]     - xyz[3 * i];
    float ry = xyz[3 * j + 1] - xyz[3 * i + 1];
    float rz = xyz[3 * j + 2] - xyz[3 * i + 2];
    float d  = sqrtf(rx * rx + ry * ry + rz * rz);
    float inv = 1.0f / d;
    float t = d * (1.0f / CUTOFF);
    if (d <= CUTOFF) {
        float env = 0.5f * (cospif(t) + 1.0f);
        g_env[e] = env;
        g_unit[3 * e]     = rx * inv;
        g_unit[3 * e + 1] = ry * inv;
        g_unit[3 * e + 2] = rz * inv;
        float s = env * inv;
        #pragma unroll
        for (int k = 0; k < NRBF; k++)
            g_rbf[e * NRBF + k] = sinpif((float)(k + 1) * t) * s;
        int pos = atomicAdd(&g_cnt[i], 1);
        if (pos < CAP) g_list[i * CAP + pos] = e;
    }
}

// ---------------------------------------------------------------------------
// phi = silu(s @ W1 + b1) @ W2 + b2  (standalone: only for conv 0)
// ---------------------------------------------------------------------------
__global__ void __launch_bounds__(256)
k_phi(const float* __restrict__ W1, const float* __restrict__ B1,
      const float* __restrict__ W2, const float* __restrict__ B2)
{
    int tid  = threadIdx.x;
    int half = tid >> 7;
    int f    = tid & 127;
    int a0   = blockIdx.x * (2 * TA) + half * TA;

    __shared__ float ssT[2][F][TA];
    __shared__ float hhT[2][F][TA];

    #pragma unroll
    for (int t = 0; t < TA; t++) ssT[half][f][t] = g_s[(a0 + t) * F + f];
    __syncthreads();

    unsigned long long acc[TA / 2];
    {
        unsigned long long b = pk2(B1[f], B1[f]);
        #pragma unroll
        for (int p = 0; p < TA / 2; p++) acc[p] = b;
    }
    for (int g = 0; g < F; g++) {
        float w = W1[g * F + f];
        unsigned long long ww = pk2(w, w);
        const unsigned long long* row = (const unsigned long long*)&ssT[half][g][0];
        #pragma unroll
        for (int p = 0; p < TA / 2; p++) FFMA2(acc[p], row[p], ww);
    }
    #pragma unroll
    for (int p = 0; p < TA / 2; p++) {
        float2 x = upk2(acc[p]);
        hhT[half][f][2 * p]     = silu(x.x);
        hhT[half][f][2 * p + 1] = silu(x.y);
    }
    __syncthreads();

    unsigned long long p0[TA / 2], p1[TA / 2], p2[TA / 2];
    {
        unsigned long long b0 = pk2(B2[f], B2[f]);
        unsigned long long b1 = pk2(B2[F + f], B2[F + f]);
        unsigned long long b2 = pk2(B2[2 * F + f], B2[2 * F + f]);
        #pragma unroll
        for (int p = 0; p < TA / 2; p++) { p0[p] = b0; p1[p] = b1; p2[p] = b2; }
    }
    for (int g = 0; g < F; g++) {
        const float* w = W2 + g * F3;
        unsigned long long w0 = pk2(w[f], w[f]);
        unsigned long long w1 = pk2(w[F + f], w[F + f]);
        unsigned long long w2 = pk2(w[2 * F + f], w[2 * F + f]);
        const unsigned long long* row = (const unsigned long long*)&hhT[half][g][0];
        #pragma unroll
        for (int p = 0; p < TA / 2; p++) {
            FFMA2(p0[p], row[p], w0);
            FFMA2(p1[p], row[p], w1);
            FFMA2(p2[p], row[p], w2);
        }
    }
    #pragma unroll
    for (int p = 0; p < TA / 2; p++) {
        float2 x0 = upk2(p0[p]), x1 = upk2(p1[p]), x2 = upk2(p2[p]);
        int a = a0 + 2 * p;
        g_phi[a * F3 + f]               = x0.x;
        g_phi[(a + 1) * F3 + f]         = x0.y;
        g_phi[a * F3 + F + f]           = x1.x;
        g_phi[(a + 1) * F3 + F + f]     = x1.y;
        g_phi[a * F3 + 2 * F + f]       = x2.x;
        g_phi[(a + 1) * F3 + 2 * F + f] = x2.y;
    }
}

// ---------------------------------------------------------------------------
// message pass over CSR buckets (R4-exact: depth-1 prefetch, 4 chains).
// ch0/ch1 rbf weights in regs as packed pairs; ch2 weights in smem.
// ---------------------------------------------------------------------------
__global__ void __launch_bounds__(128)
k_msg(const float* __restrict__ RW, const float* __restrict__ RB,
      const int* __restrict__ nbrs)
{
    __shared__ float rw2s[NRBF * F];   // ch2 weights, 10 KB
    __shared__ int   sj  [CAP];
    __shared__ float senv[CAP];
    __shared__ float sux [CAP];
    __shared__ float suy [CAP];
    __shared__ float suz [CAP];
    __shared__ float srbf[CAP][NRBF];

    int f = threadIdx.x;

    unsigned long long rw01[NRBF];
    #pragma unroll
    for (int q = 0; q < NRBF; q++)
        rw01[q] = pk2(RW[q * F3 + f], RW[q * F3 + F + f]);
    for (int idx = f; idx < NRBF * F; idx += 128) {
        int q = idx >> 7, ff = idx & 127;
        rw2s[idx] = RW[q * F3 + 2 * F + ff];
    }
    float rb0 = RB[f], rb1 = RB[F + f], rb2 = RB[2 * F + f];

    int abase = blockIdx.x * TAM;

    for (int it = 0; it < TAM; it++) {
        int a = abase + it;
        int n = g_cnt[a];
        if (n > CAP) n = CAP;

        __syncthreads();   // prev iter smem reads done; also covers rw2s fill
        if (f < n) {
            int e = g_list[a * CAP + f];
            sj  [f] = nbrs[2 * e + 1];
            senv[f] = g_env[e];
            sux [f] = g_unit[3 * e];
            suy [f] = g_unit[3 * e + 1];
            suz [f] = g_unit[3 * e + 2];
            const float4* rp = (const float4*)(g_rbf + e * NRBF);
            float4* dst = (float4*)&srbf[f][0];
            #pragma unroll
            for (int x = 0; x < NRBF / 4; x++) dst[x] = rp[x];
        }
        __syncthreads();

        float ds = 0.0f, dv0 = 0.0f, dv1 = 0.0f, dv2 = 0.0f;
        float pj0 = 0.f, pj1 = 0.f, pj2 = 0.f, vj0 = 0.f, vj1 = 0.f, vj2 = 0.f;
        if (n > 0) {
            int j = sj[0];
            const float* pj = g_phi + j * F3;
            pj0 = pj[f]; pj1 = pj[F + f]; pj2 = pj[2 * F + f];
            const float* vj = g_v + j * F3 + f * 3;
            vj0 = vj[0]; vj1 = vj[1]; vj2 = vj[2];
        }
        for (int k = 0; k < n; k++) {
            float npj0 = 0.f, npj1 = 0.f, npj2 = 0.f, nvj0 = 0.f, nvj1 = 0.f, nvj2 = 0.f;
            if (k + 1 < n) {
                int jn = sj[k + 1];
                const float* pj = g_phi + jn * F3;
                npj0 = pj[f]; npj1 = pj[F + f]; npj2 = pj[2 * F + f];
                const float* vj = g_v + jn * F3 + f * 3;
                nvj0 = vj[0]; nvj1 = vj[1]; nvj2 = vj[2];
            }
            float env = senv[k];
            unsigned long long wA = pk2(env * rb0, env * rb1);
            unsigned long long wB = pk2(0.0f, 0.0f);
            float w2a = env * rb2, w2b = 0.0f;
            #pragma unroll
            for (int q = 0; q < NRBF; q += 2) {
                float r0 = srbf[k][q];
                float r1 = srbf[k][q + 1];
                FFMA2(wA, pk2(r0, r0), rw01[q]);
                FFMA2(wB, pk2(r1, r1), rw01[q + 1]);
                w2a = fmaf(r0, rw2s[q * F + f], w2a);
                w2b = fmaf(r1, rw2s[(q + 1) * F + f], w2b);
            }
            float2 xa = upk2(wA), xb = upk2(wB);
            float w0v = xa.x + xb.x;
            float w1v = xa.y + xb.y;
            float w2v = w2a + w2b;

            float sp0 = pj0 * w0v;
            float sp1 = pj1 * w1v;
            float sp2 = pj2 * w2v;
            ds += sp1;
            dv0 += sp2 * sux[k] + sp0 * vj0;
            dv1 += sp2 * suy[k] + sp0 * vj1;
            dv2 += sp2 * suz[k] + sp0 * vj2;

            pj0 = npj0; pj1 = npj1; pj2 = npj2;
            vj0 = nvj0; vj1 = nvj1; vj2 = nvj2;
        }
        g_ds[a * F + f] = ds;
        g_dv[a * F3 + f * 3]     = dv0;
        g_dv[a * F3 + f * 3 + 1] = dv1;
        g_dv[a * F3 + f * 3 + 2] = dv2;
    }
}

// ---------------------------------------------------------------------------
// update block (256 threads = 2 halves x 8 atoms) with FUSED phi for the
// next conv layer: after writing s/v, the updated s is staged into the dead
// stT smem (upper 8 KB) and phi's two GEMM passes run inline (hidden layer
// in the lower 8 KB), writing g_phi for conv c+1.
// ---------------------------------------------------------------------------
__global__ void __launch_bounds__(256)
k_upd(const float* __restrict__ U,  const float* __restrict__ V,
      const float* __restrict__ W1, const float* __restrict__ B1,
      const float* __restrict__ W2, const float* __restrict__ B2,
      const float* __restrict__ NW1, const float* __restrict__ NB1,
      const float* __restrict__ NW2, const float* __restrict__ NB2,
      int do_phi)
{
    int tid  = threadIdx.x;
    int half = tid >> 7;
    int f    = tid & 127;
    int a0   = blockIdx.x * (2 * TA) + half * TA;

    __shared__ float svT[2][F][3][TA];    // 24 KB
    __shared__ float stT[2][2 * F][TA];   // 16 KB (aliased: shT, then sBuf/hBuf)
    float* flat = &stT[0][0][0];
    float (*shT)[F][TA] = (float (*)[F][TA])flat;  // lower 8 KB overlay
    float* hBuf = flat;                            // lower 8 KB (phi hidden)
    float* sBuf = flat + 2048;                     // upper 8 KB (phi input s)

    float snew[TA];
    #pragma unroll
    for (int t = 0; t < TA; t++) {
        int a = a0 + t;
        float s1 = g_s[a * F + f] + g_ds[a * F + f];
        snew[t]         = s1;
        stT[half][f][t] = s1;
        #pragma unroll
        for (int d = 0; d < 3; d++)
            svT[half][f][d][t] = g_v[a * F3 + f * 3 + d] + g_dv[a * F3 + f * 3 + d];
    }
    __syncthreads();

    unsigned long long ua[3][TA / 2], wa[3][TA / 2];
    #pragma unroll
    for (int d = 0; d < 3; d++)
        #pragma unroll
        for (int p = 0; p < TA / 2; p++) { ua[d][p] = 0ULL; wa[d][p] = 0ULL; }
    for (int g = 0; g < F; g++) {
        float Ug = U[g * F + f], Vg = V[g * F + f];
        unsigned long long Up = pk2(Ug, Ug), Vp = pk2(Vg, Vg);
        #pragma unroll
        for (int d = 0; d < 3; d++) {
            const unsigned long long* row = (const unsigned long long*)&svT[half][g][d][0];
            #pragma unroll
            for (int p = 0; p < TA / 2; p++) {
                unsigned long long r = row[p];
                FFMA2(ua[d][p], r, Up);
                FFMA2(wa[d][p], r, Vp);
            }
        }
    }
    float u[TA][3], uw[TA];
    #pragma unroll
    for (int p = 0; p < TA / 2; p++) {
        float wv[2][3];
        #pragma unroll
        for (int d = 0; d < 3; d++) {
            float2 xu = upk2(ua[d][p]);
            float2 xw = upk2(wa[d][p]);
            u[2 * p][d] = xu.x; u[2 * p + 1][d] = xu.y;
            wv[0][d] = xw.x;    wv[1][d] = xw.y;
        }
        #pragma unroll
        for (int h = 0; h < 2; h++) {
            int t = 2 * p + h;
            float n2 = wv[h][0] * wv[h][0] + wv[h][1] * wv[h][1] + wv[h][2] * wv[h][2];
            stT[half][F + f][t] = sqrtf(n2 + 1e-15f);
            uw[t] = u[t][0] * wv[h][0] + u[t][1] * wv[h][1] + u[t][2] * wv[h][2];
        }
    }
    __syncthreads();

    unsigned long long hacc[TA / 2];
    {
        unsigned long long b = pk2(B1[f], B1[f]);
        #pragma unroll
        for (int p = 0; p < TA / 2; p++) hacc[p] = b;
    }
    for (int r = 0; r < 2 * F; r++) {
        float wv = W1[r * F + f];
        unsigned long long ww = pk2(wv, wv);
        const unsigned long long* row = (const unsigned long long*)&stT[half][r][0];
        #pragma unroll
        for (int p = 0; p < TA / 2; p++) FFMA2(hacc[p], row[p], ww);
    }
    __syncthreads();   // all stT reads complete before aliased shT writes
    #pragma unroll
    for (int p = 0; p < TA / 2; p++) {
        float2 x = upk2(hacc[p]);
        shT[half][f][2 * p]     = silu(x.x);
        shT[half][f][2 * p + 1] = silu(x.y);
    }
    __syncthreads();

    unsigned long long p0[TA / 2], p1[TA / 2], p2[TA / 2];
    {
        unsigned long long b0 = pk2(B2[f], B2[f]);
        unsigned long long b1 = pk2(B2[F + f], B2[F + f]);
        unsigned long long b2 = pk2(B2[2 * F + f], B2[2 * F + f]);
        #pragma unroll
        for (int p = 0; p < TA / 2; p++) { p0[p] = b0; p1[p] = b1; p2[p] = b2; }
    }
    for (int g = 0; g < F; g++) {
        const float* wr = W2 + g * F3;
        unsigned long long w0 = pk2(wr[f], wr[f]);
        unsigned long long w1 = pk2(wr[F + f], wr[F + f]);
        unsigned long long w2 = pk2(wr[2 * F + f], wr[2 * F + f]);
        const unsigned long long* row = (const unsigned long long*)&shT[half][g][0];
        #pragma unroll
        for (int p = 0; p < TA / 2; p++) {
            FFMA2(p0[p], row[p], w0);
            FFMA2(p1[p], row[p], w1);
            FFMA2(p2[p], row[p], w2);
        }
    }
    #pragma unroll
    for (int p = 0; p < TA / 2; p++) {
        float2 avv = upk2(p0[p]), asv = upk2(p1[p]), ass = upk2(p2[p]);
        #pragma unroll
        for (int h = 0; h < 2; h++) {
            int t = 2 * p + h;
            int a = a0 + t;
            float a_vv = h ? avv.y : avv.x;
            float a_sv = h ? asv.y : asv.x;
            float a_ss = h ? ass.y : ass.x;
            float sfin = snew[t] + uw[t] * a_sv + a_ss;
            g_s[a * F + f] = sfin;
            sBuf[half * 1024 + f * TA + t] = sfin;   // upper 8 KB, disjoint from shT
            #pragma unroll
            for (int d = 0; d < 3; d++)
                g_v[a * F3 + f * 3 + d] = svT[half][f][d][t] + u[t][d] * a_vv;
        }
    }

    // ---- fused phi for next conv: g_phi = silu(s@NW1+NB1)@NW2 + NB2 ----
    if (do_phi) {
        __syncthreads();  // sBuf complete; shT reads complete
        unsigned long long acc[TA / 2];
        {
            unsigned long long b = pk2(NB1[f], NB1[f]);
            #pragma unroll
            for (int p = 0; p < TA / 2; p++) acc[p] = b;
        }
        for (int g = 0; g < F; g++) {
            float w = NW1[g * F + f];
            unsigned long long ww = pk2(w, w);
            const unsigned long long* row =
                (const unsigned long long*)(sBuf + half * 1024 + g * TA);
            #pragma unroll
            for (int p = 0; p < TA / 2; p++) FFMA2(acc[p], row[p], ww);
        }
        #pragma unroll
        for (int p = 0; p < TA / 2; p++) {
            float2 x = upk2(acc[p]);
            hBuf[half * 1024 + f * TA + 2 * p]     = silu(x.x);
            hBuf[half * 1024 + f * TA + 2 * p + 1] = silu(x.y);
        }
        __syncthreads();

        unsigned long long q0[TA / 2], q1[TA / 2], q2[TA / 2];
        {
            unsigned long long b0 = pk2(NB2[f], NB2[f]);
            unsigned long long b1 = pk2(NB2[F + f], NB2[F + f]);
            unsigned long long b2 = pk2(NB2[2 * F + f], NB2[2 * F + f]);
            #pragma unroll
            for (int p = 0; p < TA / 2; p++) { q0[p] = b0; q1[p] = b1; q2[p] = b2; }
        }
        for (int g = 0; g < F; g++) {
            const float* w = NW2 + g * F3;
            unsigned long long w0 = pk2(w[f], w[f]);
            unsigned long long w1 = pk2(w[F + f], w[F + f]);
            unsigned long long w2 = pk2(w[2 * F + f], w[2 * F + f]);
            const unsigned long long* row =
                (const unsigned long long*)(hBuf + half * 1024 + g * TA);
            #pragma unroll
            for (int p = 0; p < TA / 2; p++) {
                FFMA2(q0[p], row[p], w0);
                FFMA2(q1[p], row[p], w1);
                FFMA2(q2[p], row[p], w2);
            }
        }
        #pragma unroll
        for (int p = 0; p < TA / 2; p++) {
            float2 x0 = upk2(q0[p]), x1 = upk2(q1[p]), x2 = upk2(q2[p]);
            int a = a0 + 2 * p;
            g_phi[a * F3 + f]               = x0.x;
            g_phi[(a + 1) * F3 + f]         = x0.y;
            g_phi[a * F3 + F + f]           = x1.x;
            g_phi[(a + 1) * F3 + F + f]     = x1.y;
            g_phi[a * F3 + 2 * F + f]       = x2.x;
            g_phi[(a + 1) * F3 + 2 * F + f] = x2.y;
        }
    }
}

// ---------------------------------------------------------------------------
// readout: 16 atoms per block
// ---------------------------------------------------------------------------
#define TR 16

__global__ void k_zero_out(float* out)
{
    int t = threadIdx.x;
    if (t < NMOLS) out[t] = 0.0f;
}

__global__ void __launch_bounds__(128)
k_readout(const float* __restrict__ W1, const float* __restrict__ B1,
          const float* __restrict__ W2, const float* __restrict__ B2,
          const int* __restrict__ mol, float* __restrict__ out)
{
    int tid  = threadIdx.x;
    int half = tid >> 6;
    int t    = tid & 63;
    int ab   = blockIdx.x * TR;

    __shared__ float ssT[F][TR];
    __shared__ float red[TR][64];

    for (int x = tid; x < TR * F; x += 128) {
        int aa = x >> 7, ff = x & 127;
        ssT[ff][aa] = g_s[(ab + aa) * F + ff];
    }
    __syncthreads();

    unsigned long long acc[4];
    {
        unsigned long long b = pk2(B1[t], B1[t]);
        #pragma unroll
        for (int p = 0; p < 4; p++) acc[p] = b;
    }
    for (int g = 0; g < F; g++) {
        float w = W1[g * 64 + t];
        unsigned long long ww = pk2(w, w);
        const unsigned long long* row = (const unsigned long long*)&ssT[g][half * 8];
        #pragma unroll
        for (int p = 0; p < 4; p++) FFMA2(acc[p], row[p], ww);
    }
    float w2v = W2[t];
    #pragma unroll
    for (int p = 0; p < 4; p++) {
        float2 x = upk2(acc[p]);
        red[half * 8 + 2 * p][t]     = silu(x.x) * w2v;
        red[half * 8 + 2 * p + 1][t] = silu(x.y) * w2v;
    }
    __syncthreads();

    if (tid < TR) {
        float e = B2[0];
        #pragma unroll
        for (int q = 0; q < 64; q++) e += red[tid][q];
        atomicAdd(&out[mol[ab + tid]], e);
    }
}

// ---------------------------------------------------------------------------
// launch
// ---------------------------------------------------------------------------
extern "C" void kernel_launch(void* const* d_in, const int* in_sizes, int n_in,
                              void* d_out, int out_size)
{
    const float* xyz    = (const float*)d_in[0];
    const float* emb    = (const float*)d_in[1];
    const float* msg_w1 = (const float*)d_in[2];
    const float* msg_b1 = (const float*)d_in[3];
    const float* msg_w2 = (const float*)d_in[4];
    const float* msg_b2 = (const float*)d_in[5];
    const float* rbf_w  = (const float*)d_in[6];
    const float* rbf_b  = (const float*)d_in[7];
    const float* upd_u  = (const float*)d_in[8];
    const float* upd_v  = (const float*)d_in[9];
    const float* upd_w1 = (const float*)d_in[10];
    const float* upd_b1 = (const float*)d_in[11];
    const float* upd_w2 = (const float*)d_in[12];
    const float* upd_b2 = (const float*)d_in[13];
    const float* ro_w1  = (const float*)d_in[14];
    const float* ro_b1  = (const float*)d_in[15];
    const float* ro_w2  = (const float*)d_in[16];
    const float* ro_b2  = (const float*)d_in[17];
    const int*   z      = (const int*)d_in[18];
    const int*   nbrs   = (const int*)d_in[19];
    const int*   mol    = (const int*)d_in[20];
    float*       out    = (float*)d_out;

    int E = in_sizes[19] / 2;

    k_init <<<NATOMS, 128>>>(emb, z);
    k_edges<<<(E + 255) / 256, 256>>>(xyz, nbrs, E);

    // phi for conv 0
    k_phi<<<NATOMS / (2 * TA), 256>>>(msg_w1, msg_b1, msg_w2, msg_b2);

    for (int c = 0; c < NCONV; c++) {
        k_msg<<<NATOMS / TAM, 128>>>(rbf_w + c * NRBF * F3, rbf_b + c * F3, nbrs);
        int nc = (c + 1 < NCONV) ? (c + 1) : c;   // dummy ptrs when do_phi=0
        k_upd<<<NATOMS / (2 * TA), 256>>>(
            upd_u  + c * F * F,      upd_v  + c * F * F,
            upd_w1 + c * 2 * F * F,  upd_b1 + c * F,
            upd_w2 + c * F * F3,     upd_b2 + c * F3,
            msg_w1 + nc * F * F,     msg_b1 + nc * F,
            msg_w2 + nc * F * F3,    msg_b2 + nc * F3,
            (c + 1 < NCONV) ? 1 : 0);
    }

    k_zero_out<<<1, 128>>>(out);
    k_readout <<<NATOMS / TR, 128>>>(ro_w1, ro_b1, ro_w2, ro_b2, mol, out);
}

// round 9
// speedup vs baseline: 1.0428x; 1.0428x over previous
#include <cuda_runtime.h>
#include <math.h>

// ---- problem constants ----
#define F      128
#define F3     384
#define NRBF   20
#define NATOMS 8000
#define NEDGES 160000
#define NMOLS  100
#define NCONV  3
#define CUTOFF 5.0f

#define TA  8    // atoms per half in phi/upd kernels (16 per block)
#define TAM 4    // atoms per block in msg kernel
#define CAP 64   // max active edges per destination atom

// ---- device scratch ----
__device__ float g_s   [NATOMS * F];
__device__ float g_v   [NATOMS * F3];
__device__ float g_ds  [NATOMS * F];
__device__ float g_dv  [NATOMS * F3];
__device__ float g_phi [NATOMS * F3];
__device__ float g_rbf [NEDGES * NRBF];   // env-premultiplied
__device__ float g_env [NEDGES];
__device__ float g_unit[NEDGES * 3];
__device__ int   g_cnt [NATOMS];
__device__ int   g_list[NATOMS * CAP];
// k_upd fission scratch
__device__ float g_uv  [NATOMS * F3];     // u_v  [a][f][3]
__device__ float g_uw  [NATOMS * F];      // dot(u_v, v_v) per (a,f)
__device__ float g_norm[NATOMS * F];      // |v_v| per (a,f)

__device__ __forceinline__ float silu(float x) { return x / (1.0f + __expf(-x)); }

// packed fp32x2 helpers
#define FFMA2(acc, a, b) asm("fma.rn.f32x2 %0, %1, %2, %0;" : "+l"(acc) : "l"(a), "l"(b))
__device__ __forceinline__ unsigned long long pk2(float x, float y) {
    unsigned long long r; asm("mov.b64 %0, {%1, %2};" : "=l"(r) : "f"(x), "f"(y)); return r;
}
__device__ __forceinline__ float2 upk2(unsigned long long v) {
    float2 o; asm("mov.b64 {%0, %1}, %2;" : "=f"(o.x), "=f"(o.y) : "l"(v)); return o;
}

// ---------------------------------------------------------------------------
// init
// ---------------------------------------------------------------------------
__global__ void k_init(const float* __restrict__ emb, const int* __restrict__ z)
{
    int a = blockIdx.x, f = threadIdx.x;
    g_s[a * F + f] = emb[z[a] * F + f];
    int b = a * F3 + f * 3;
    g_v[b] = 0.0f; g_v[b + 1] = 0.0f; g_v[b + 2] = 0.0f;
    if (f == 0) g_cnt[a] = 0;
}

// ---------------------------------------------------------------------------
// edge geometry + CSR build
// ---------------------------------------------------------------------------
__global__ void k_edges(const float* __restrict__ xyz, const int* __restrict__ nbrs, int E)
{
    int e = blockIdx.x * 256 + threadIdx.x;
    if (e >= E) return;
    int i = nbrs[2 * e], j = nbrs[2 * e + 1];
    float rx = xyz[3 * j]     - xyz[3 * i];
    float ry = xyz[3 * j + 1] - xyz[3 * i + 1];
    float rz = xyz[3 * j + 2] - xyz[3 * i + 2];
    float d  = sqrtf(rx * rx + ry * ry + rz * rz);
    float inv = 1.0f / d;
    float t = d * (1.0f / CUTOFF);
    if (d <= CUTOFF) {
        float env = 0.5f * (cospif(t) + 1.0f);
        g_env[e] = env;
        g_unit[3 * e]     = rx * inv;
        g_unit[3 * e + 1] = ry * inv;
        g_unit[3 * e + 2] = rz * inv;
        float s = env * inv;
        #pragma unroll
        for (int k = 0; k < NRBF; k++)
            g_rbf[e * NRBF + k] = sinpif((float)(k + 1) * t) * s;
        int pos = atomicAdd(&g_cnt[i], 1);
        if (pos < CAP) g_list[i * CAP + pos] = e;
    }
}

// ---------------------------------------------------------------------------
// phi = silu(s @ W1 + b1) @ W2 + b2   (256 threads = 2 halves, 16 atoms/block)
// ---------------------------------------------------------------------------
__global__ void __launch_bounds__(256)
k_phi(const float* __restrict__ W1, const float* __restrict__ B1,
      const float* __restrict__ W2, const float* __restrict__ B2)
{
    int tid  = threadIdx.x;
    int half = tid >> 7;
    int f    = tid & 127;
    int a0   = blockIdx.x * (2 * TA) + half * TA;

    __shared__ float ssT[2][F][TA];
    __shared__ float hhT[2][F][TA];

    #pragma unroll
    for (int t = 0; t < TA; t++) ssT[half][f][t] = g_s[(a0 + t) * F + f];
    __syncthreads();

    unsigned long long acc[TA / 2];
    {
        unsigned long long b = pk2(B1[f], B1[f]);
        #pragma unroll
        for (int p = 0; p < TA / 2; p++) acc[p] = b;
    }
    for (int g = 0; g < F; g++) {
        float w = W1[g * F + f];
        unsigned long long ww = pk2(w, w);
        const unsigned long long* row = (const unsigned long long*)&ssT[half][g][0];
        #pragma unroll
        for (int p = 0; p < TA / 2; p++) FFMA2(acc[p], row[p], ww);
    }
    #pragma unroll
    for (int p = 0; p < TA / 2; p++) {
        float2 x = upk2(acc[p]);
        hhT[half][f][2 * p]     = silu(x.x);
        hhT[half][f][2 * p + 1] = silu(x.y);
    }
    __syncthreads();

    unsigned long long p0[TA / 2], p1[TA / 2], p2[TA / 2];
    {
        unsigned long long b0 = pk2(B2[f], B2[f]);
        unsigned long long b1 = pk2(B2[F + f], B2[F + f]);
        unsigned long long b2 = pk2(B2[2 * F + f], B2[2 * F + f]);
        #pragma unroll
        for (int p = 0; p < TA / 2; p++) { p0[p] = b0; p1[p] = b1; p2[p] = b2; }
    }
    for (int g = 0; g < F; g++) {
        const float* w = W2 + g * F3;
        unsigned long long w0 = pk2(w[f], w[f]);
        unsigned long long w1 = pk2(w[F + f], w[F + f]);
        unsigned long long w2 = pk2(w[2 * F + f], w[2 * F + f]);
        const unsigned long long* row = (const unsigned long long*)&hhT[half][g][0];
        #pragma unroll
        for (int p = 0; p < TA / 2; p++) {
            FFMA2(p0[p], row[p], w0);
            FFMA2(p1[p], row[p], w1);
            FFMA2(p2[p], row[p], w2);
        }
    }
    #pragma unroll
    for (int p = 0; p < TA / 2; p++) {
        float2 x0 = upk2(p0[p]), x1 = upk2(p1[p]), x2 = upk2(p2[p]);
        int a = a0 + 2 * p;
        g_phi[a * F3 + f]               = x0.x;
        g_phi[(a + 1) * F3 + f]         = x0.y;
        g_phi[a * F3 + F + f]           = x1.x;
        g_phi[(a + 1) * F3 + F + f]     = x1.y;
        g_phi[a * F3 + 2 * F + f]       = x2.x;
        g_phi[(a + 1) * F3 + 2 * F + f] = x2.y;
    }
}

// ---------------------------------------------------------------------------
// message pass over CSR buckets (R4-exact)
// ---------------------------------------------------------------------------
__global__ void __launch_bounds__(128)
k_msg(const float* __restrict__ RW, const float* __restrict__ RB,
      const int* __restrict__ nbrs)
{
    __shared__ float rw2s[NRBF * F];   // ch2 weights, 10 KB
    __shared__ int   sj  [CAP];
    __shared__ float senv[CAP];
    __shared__ float sux [CAP];
    __shared__ float suy [CAP];
    __shared__ float suz [CAP];
    __shared__ float srbf[CAP][NRBF];

    int f = threadIdx.x;

    unsigned long long rw01[NRBF];
    #pragma unroll
    for (int q = 0; q < NRBF; q++)
        rw01[q] = pk2(RW[q * F3 + f], RW[q * F3 + F + f]);
    for (int idx = f; idx < NRBF * F; idx += 128) {
        int q = idx >> 7, ff = idx & 127;
        rw2s[idx] = RW[q * F3 + 2 * F + ff];
    }
    float rb0 = RB[f], rb1 = RB[F + f], rb2 = RB[2 * F + f];

    int abase = blockIdx.x * TAM;

    for (int it = 0; it < TAM; it++) {
        int a = abase + it;
        int n = g_cnt[a];
        if (n > CAP) n = CAP;

        __syncthreads();
        if (f < n) {
            int e = g_list[a * CAP + f];
            sj  [f] = nbrs[2 * e + 1];
            senv[f] = g_env[e];
            sux [f] = g_unit[3 * e];
            suy [f] = g_unit[3 * e + 1];
            suz [f] = g_unit[3 * e + 2];
            const float4* rp = (const float4*)(g_rbf + e * NRBF);
            float4* dst = (float4*)&srbf[f][0];
            #pragma unroll
            for (int x = 0; x < NRBF / 4; x++) dst[x] = rp[x];
        }
        __syncthreads();

        float ds = 0.0f, dv0 = 0.0f, dv1 = 0.0f, dv2 = 0.0f;
        float pj0 = 0.f, pj1 = 0.f, pj2 = 0.f, vj0 = 0.f, vj1 = 0.f, vj2 = 0.f;
        if (n > 0) {
            int j = sj[0];
            const float* pj = g_phi + j * F3;
            pj0 = pj[f]; pj1 = pj[F + f]; pj2 = pj[2 * F + f];
            const float* vj = g_v + j * F3 + f * 3;
            vj0 = vj[0]; vj1 = vj[1]; vj2 = vj[2];
        }
        for (int k = 0; k < n; k++) {
            float npj0 = 0.f, npj1 = 0.f, npj2 = 0.f, nvj0 = 0.f, nvj1 = 0.f, nvj2 = 0.f;
            if (k + 1 < n) {
                int jn = sj[k + 1];
                const float* pj = g_phi + jn * F3;
                npj0 = pj[f]; npj1 = pj[F + f]; npj2 = pj[2 * F + f];
                const float* vj = g_v + jn * F3 + f * 3;
                nvj0 = vj[0]; nvj1 = vj[1]; nvj2 = vj[2];
            }
            float env = senv[k];
            unsigned long long wA = pk2(env * rb0, env * rb1);
            unsigned long long wB = pk2(0.0f, 0.0f);
            float w2a = env * rb2, w2b = 0.0f;
            #pragma unroll
            for (int q = 0; q < NRBF; q += 2) {
                float r0 = srbf[k][q];
                float r1 = srbf[k][q + 1];
                FFMA2(wA, pk2(r0, r0), rw01[q]);
                FFMA2(wB, pk2(r1, r1), rw01[q + 1]);
                w2a = fmaf(r0, rw2s[q * F + f], w2a);
                w2b = fmaf(r1, rw2s[(q + 1) * F + f], w2b);
            }
            float2 xa = upk2(wA), xb = upk2(wB);
            float w0v = xa.x + xb.x;
            float w1v = xa.y + xb.y;
            float w2v = w2a + w2b;

            float sp0 = pj0 * w0v;
            float sp1 = pj1 * w1v;
            float sp2 = pj2 * w2v;
            ds += sp1;
            dv0 += sp2 * sux[k] + sp0 * vj0;
            dv1 += sp2 * suy[k] + sp0 * vj1;
            dv2 += sp2 * suz[k] + sp0 * vj2;

            pj0 = npj0; pj1 = npj1; pj2 = npj2;
            vj0 = nvj0; vj1 = nvj1; vj2 = nvj2;
        }
        g_ds[a * F + f] = ds;
        g_dv[a * F3 + f * 3]     = dv0;
        g_dv[a * F3 + f * 3 + 1] = dv1;
        g_dv[a * F3 + f * 3 + 2] = dv2;
    }
}

// ---------------------------------------------------------------------------
// k_updA: s/v message update + UV linear pass.
// Writes: g_s = s+ds, g_v = v+dv, g_uv = u_v, g_norm = |v_v|, g_uw = u.v
// ---------------------------------------------------------------------------
__global__ void __launch_bounds__(256)
k_updA(const float* __restrict__ U, const float* __restrict__ V)
{
    int tid  = threadIdx.x;
    int half = tid >> 7;
    int f    = tid & 127;
    int a0   = blockIdx.x * (2 * TA) + half * TA;

    __shared__ float svT[2][F][3][TA];    // 24 KB

    #pragma unroll
    for (int t = 0; t < TA; t++) {
        int a = a0 + t;
        g_s[a * F + f] = g_s[a * F + f] + g_ds[a * F + f];
        #pragma unroll
        for (int d = 0; d < 3; d++)
            svT[half][f][d][t] = g_v[a * F3 + f * 3 + d] + g_dv[a * F3 + f * 3 + d];
    }
    __syncthreads();

    unsigned long long ua[3][TA / 2], wa[3][TA / 2];
    #pragma unroll
    for (int d = 0; d < 3; d++)
        #pragma unroll
        for (int p = 0; p < TA / 2; p++) { ua[d][p] = 0ULL; wa[d][p] = 0ULL; }
    for (int g = 0; g < F; g++) {
        float Ug = U[g * F + f], Vg = V[g * F + f];
        unsigned long long Up = pk2(Ug, Ug), Vp = pk2(Vg, Vg);
        #pragma unroll
        for (int d = 0; d < 3; d++) {
            const unsigned long long* row = (const unsigned long long*)&svT[half][g][d][0];
            #pragma unroll
            for (int p = 0; p < TA / 2; p++) {
                unsigned long long r = row[p];
                FFMA2(ua[d][p], r, Up);
                FFMA2(wa[d][p], r, Vp);
            }
        }
    }

    #pragma unroll
    for (int p = 0; p < TA / 2; p++) {
        float uloc[2][3], wloc[2][3];
        #pragma unroll
        for (int d = 0; d < 3; d++) {
            float2 xu = upk2(ua[d][p]);
            float2 xw = upk2(wa[d][p]);
            uloc[0][d] = xu.x; uloc[1][d] = xu.y;
            wloc[0][d] = xw.x; wloc[1][d] = xw.y;
        }
        #pragma unroll
        for (int h = 0; h < 2; h++) {
            int a = a0 + 2 * p + h;
            float n2 = wloc[h][0]*wloc[h][0] + wloc[h][1]*wloc[h][1] + wloc[h][2]*wloc[h][2];
            g_norm[a * F + f] = sqrtf(n2 + 1e-15f);
            g_uw  [a * F + f] = uloc[h][0]*wloc[h][0] + uloc[h][1]*wloc[h][1] + uloc[h][2]*wloc[h][2];
            #pragma unroll
            for (int d = 0; d < 3; d++)
                g_uv[a * F3 + f * 3 + d] = uloc[h][d];
        }
    }

    // v base (v + dv) out
    #pragma unroll
    for (int t = 0; t < TA; t++) {
        int a = a0 + t;
        #pragma unroll
        for (int d = 0; d < 3; d++)
            g_v[a * F3 + f * 3 + d] = svT[half][f][d][t];
    }
}

// ---------------------------------------------------------------------------
// k_updB: gated MLP + final s/v writes.
// stack = [g_s, g_norm]; a = silu(stack@W1+b1)@W2+b2
// g_s += uw*a_sv + a_ss ; g_v += g_uv*a_vv
// ---------------------------------------------------------------------------
__global__ void __launch_bounds__(256)
k_updB(const float* __restrict__ W1, const float* __restrict__ B1,
       const float* __restrict__ W2, const float* __restrict__ B2)
{
    int tid  = threadIdx.x;
    int half = tid >> 7;
    int f    = tid & 127;
    int a0   = blockIdx.x * (2 * TA) + half * TA;

    __shared__ float stT[2][2 * F][TA];   // 16 KB (lower 8 KB reused as shT)
    float (*shT)[F][TA] = (float (*)[F][TA])&stT[0][0][0];

    float snew[TA];
    #pragma unroll
    for (int t = 0; t < TA; t++) {
        int a = a0 + t;
        float s1 = g_s[a * F + f];
        snew[t]             = s1;
        stT[half][f][t]     = s1;
        stT[half][F + f][t] = g_norm[a * F + f];
    }
    __syncthreads();

    unsigned long long hacc[TA / 2];
    {
        unsigned long long b = pk2(B1[f], B1[f]);
        #pragma unroll
        for (int p = 0; p < TA / 2; p++) hacc[p] = b;
    }
    for (int r = 0; r < 2 * F; r++) {
        float wv = W1[r * F + f];
        unsigned long long ww = pk2(wv, wv);
        const unsigned long long* row = (const unsigned long long*)&stT[half][r][0];
        #pragma unroll
        for (int p = 0; p < TA / 2; p++) FFMA2(hacc[p], row[p], ww);
    }
    __syncthreads();   // all stack reads done before aliased shT writes
    #pragma unroll
    for (int p = 0; p < TA / 2; p++) {
        float2 x = upk2(hacc[p]);
        shT[half][f][2 * p]     = silu(x.x);
        shT[half][f][2 * p + 1] = silu(x.y);
    }
    __syncthreads();

    unsigned long long p0[TA / 2], p1[TA / 2], p2[TA / 2];
    {
        unsigned long long b0 = pk2(B2[f], B2[f]);
        unsigned long long b1 = pk2(B2[F + f], B2[F + f]);
        unsigned long long b2 = pk2(B2[2 * F + f], B2[2 * F + f]);
        #pragma unroll
        for (int p = 0; p < TA / 2; p++) { p0[p] = b0; p1[p] = b1; p2[p] = b2; }
    }
    for (int g = 0; g < F; g++) {
        const float* wr = W2 + g * F3;
        unsigned long long w0 = pk2(wr[f], wr[f]);
        unsigned long long w1 = pk2(wr[F + f], wr[F + f]);
        unsigned long long w2 = pk2(wr[2 * F + f], wr[2 * F + f]);
        const unsigned long long* row = (const unsigned long long*)&shT[half][g][0];
        #pragma unroll
        for (int p = 0; p < TA / 2; p++) {
            FFMA2(p0[p], row[p], w0);
            FFMA2(p1[p], row[p], w1);
            FFMA2(p2[p], row[p], w2);
        }
    }
    #pragma unroll
    for (int p = 0; p < TA / 2; p++) {
        float2 avv = upk2(p0[p]), asv = upk2(p1[p]), ass = upk2(p2[p]);
        #pragma unroll
        for (int h = 0; h < 2; h++) {
            int t = 2 * p + h;
            int a = a0 + t;
            float a_vv = h ? avv.y : avv.x;
            float a_sv = h ? asv.y : asv.x;
            float a_ss = h ? ass.y : ass.x;
            g_s[a * F + f] = snew[t] + g_uw[a * F + f] * a_sv + a_ss;
            #pragma unroll
            for (int d = 0; d < 3; d++) {
                int idx = a * F3 + f * 3 + d;
                g_v[idx] = g_v[idx] + g_uv[idx] * a_vv;
            }
        }
    }
}

// ---------------------------------------------------------------------------
// readout: 16 atoms per block
// ---------------------------------------------------------------------------
#define TR 16

__global__ void k_zero_out(float* out)
{
    int t = threadIdx.x;
    if (t < NMOLS) out[t] = 0.0f;
}

__global__ void __launch_bounds__(128)
k_readout(const float* __restrict__ W1, const float* __restrict__ B1,
          const float* __restrict__ W2, const float* __restrict__ B2,
          const int* __restrict__ mol, float* __restrict__ out)
{
    int tid  = threadIdx.x;
    int half = tid >> 6;
    int t    = tid & 63;
    int ab   = blockIdx.x * TR;

    __shared__ float ssT[F][TR];
    __shared__ float red[TR][64];

    for (int x = tid; x < TR * F; x += 128) {
        int aa = x >> 7, ff = x & 127;
        ssT[ff][aa] = g_s[(ab + aa) * F + ff];
    }
    __syncthreads();

    unsigned long long acc[4];
    {
        unsigned long long b = pk2(B1[t], B1[t]);
        #pragma unroll
        for (int p = 0; p < 4; p++) acc[p] = b;
    }
    for (int g = 0; g < F; g++) {
        float w = W1[g * 64 + t];
        unsigned long long ww = pk2(w, w);
        const unsigned long long* row = (const unsigned long long*)&ssT[g][half * 8];
        #pragma unroll
        for (int p = 0; p < 4; p++) FFMA2(acc[p], row[p], ww);
    }
    float w2v = W2[t];
    #pragma unroll
    for (int p = 0; p < 4; p++) {
        float2 x = upk2(acc[p]);
        red[half * 8 + 2 * p][t]     = silu(x.x) * w2v;
        red[half * 8 + 2 * p + 1][t] = silu(x.y) * w2v;
    }
    __syncthreads();

    if (tid < TR) {
        float e = B2[0];
        #pragma unroll
        for (int q = 0; q < 64; q++) e += red[tid][q];
        atomicAdd(&out[mol[ab + tid]], e);
    }
}

// ---------------------------------------------------------------------------
// launch
// ---------------------------------------------------------------------------
extern "C" void kernel_launch(void* const* d_in, const int* in_sizes, int n_in,
                              void* d_out, int out_size)
{
    const float* xyz    = (const float*)d_in[0];
    const float* emb    = (const float*)d_in[1];
    const float* msg_w1 = (const float*)d_in[2];
    const float* msg_b1 = (const float*)d_in[3];
    const float* msg_w2 = (const float*)d_in[4];
    const float* msg_b2 = (const float*)d_in[5];
    const float* rbf_w  = (const float*)d_in[6];
    const float* rbf_b  = (const float*)d_in[7];
    const float* upd_u  = (const float*)d_in[8];
    const float* upd_v  = (const float*)d_in[9];
    const float* upd_w1 = (const float*)d_in[10];
    const float* upd_b1 = (const float*)d_in[11];
    const float* upd_w2 = (const float*)d_in[12];
    const float* upd_b2 = (const float*)d_in[13];
    const float* ro_w1  = (const float*)d_in[14];
    const float* ro_b1  = (const float*)d_in[15];
    const float* ro_w2  = (const float*)d_in[16];
    const float* ro_b2  = (const float*)d_in[17];
    const int*   z      = (const int*)d_in[18];
    const int*   nbrs   = (const int*)d_in[19];
    const int*   mol    = (const int*)d_in[20];
    float*       out    = (float*)d_out;

    int E = in_sizes[19] / 2;

    k_init <<<NATOMS, 128>>>(emb, z);
    k_edges<<<(E + 255) / 256, 256>>>(xyz, nbrs, E);

    for (int c = 0; c < NCONV; c++) {
        k_phi <<<NATOMS / (2 * TA), 256>>>(msg_w1 + c * F * F,  msg_b1 + c * F,
                                           msg_w2 + c * F * F3, msg_b2 + c * F3);
        k_msg <<<NATOMS / TAM, 128>>>(rbf_w + c * NRBF * F3, rbf_b + c * F3, nbrs);
        k_updA<<<NATOMS / (2 * TA), 256>>>(upd_u + c * F * F, upd_v + c * F * F);
        k_updB<<<NATOMS / (2 * TA), 256>>>(upd_w1 + c * 2 * F * F, upd_b1 + c * F,
                                           upd_w2 + c * F * F3,    upd_b2 + c * F3);
    }

    k_zero_out<<<1, 128>>>(out);
    k_readout <<<NATOMS / TR, 128>>>(ro_w1, ro_b1, ro_w2, ro_b2, mol, out);
}

// round 10
// speedup vs baseline: 1.0798x; 1.0354x over previous
#include <cuda_runtime.h>
#include <math.h>

// ---- problem constants ----
#define F      128
#define F3     384
#define NRBF   20
#define NATOMS 8000
#define NEDGES 160000
#define NMOLS  100
#define NCONV  3
#define CUTOFF 5.0f

#define TA  8    // atoms per half in phi/upd kernels (16 per block)
#define TAM 4    // atoms per block in msg kernel
#define CAP 64   // max active edges per destination atom

// ---- device scratch ----
__device__ float g_s   [NATOMS * F];
__device__ float g_v   [NATOMS * F3];
__device__ float g_ds  [NATOMS * F];
__device__ float g_dv  [NATOMS * F3];
__device__ float g_phi [NATOMS * F3];
__device__ float g_rbf [NEDGES * NRBF];   // env-premultiplied
__device__ float g_env [NEDGES];
__device__ float g_unit[NEDGES * 3];
__device__ int   g_cnt [NATOMS];
__device__ int   g_list[NATOMS * CAP];

__device__ __forceinline__ float silu(float x) { return x / (1.0f + __expf(-x)); }

// packed fp32x2 helpers
#define FFMA2(acc, a, b) asm("fma.rn.f32x2 %0, %1, %2, %0;" : "+l"(acc) : "l"(a), "l"(b))
__device__ __forceinline__ unsigned long long pk2(float x, float y) {
    unsigned long long r; asm("mov.b64 %0, {%1, %2};" : "=l"(r) : "f"(x), "f"(y)); return r;
}
__device__ __forceinline__ float2 upk2(unsigned long long v) {
    float2 o; asm("mov.b64 {%0, %1}, %2;" : "=f"(o.x), "=f"(o.y) : "l"(v)); return o;
}

// ---------------------------------------------------------------------------
// init
// ---------------------------------------------------------------------------
__global__ void k_init(const float* __restrict__ emb, const int* __restrict__ z)
{
    int a = blockIdx.x, f = threadIdx.x;
    g_s[a * F + f] = emb[z[a] * F + f];
    int b = a * F3 + f * 3;
    g_v[b] = 0.0f; g_v[b + 1] = 0.0f; g_v[b + 2] = 0.0f;
    if (f == 0) g_cnt[a] = 0;
}

// ---------------------------------------------------------------------------
// edge geometry + CSR build
// ---------------------------------------------------------------------------
__global__ void k_edges(const float* __restrict__ xyz, const int* __restrict__ nbrs, int E)
{
    int e = blockIdx.x * 256 + threadIdx.x;
    if (e >= E) return;
    int i = nbrs[2 * e], j = nbrs[2 * e + 1];
    float rx = xyz[3 * j]     - xyz[3 * i];
    float ry = xyz[3 * j + 1] - xyz[3 * i + 1];
    float rz = xyz[3 * j + 2] - xyz[3 * i + 2];
    float d  = sqrtf(rx * rx + ry * ry + rz * rz);
    float inv = 1.0f / d;
    float t = d * (1.0f / CUTOFF);
    if (d <= CUTOFF) {
        float env = 0.5f * (cospif(t) + 1.0f);
        g_env[e] = env;
        g_unit[3 * e]     = rx * inv;
        g_unit[3 * e + 1] = ry * inv;
        g_unit[3 * e + 2] = rz * inv;
        float s = env * inv;
        #pragma unroll
        for (int k = 0; k < NRBF; k++)
            g_rbf[e * NRBF + k] = sinpif((float)(k + 1) * t) * s;
        int pos = atomicAdd(&g_cnt[i], 1);
        if (pos < CAP) g_list[i * CAP + pos] = e;
    }
}

// ---------------------------------------------------------------------------
// phi = silu(s @ W1 + b1) @ W2 + b2   (256 threads = 2 halves, 16 atoms/block)
// ---------------------------------------------------------------------------
__global__ void __launch_bounds__(256)
k_phi(const float* __restrict__ W1, const float* __restrict__ B1,
      const float* __restrict__ W2, const float* __restrict__ B2)
{
    int tid  = threadIdx.x;
    int half = tid >> 7;
    int f    = tid & 127;
    int a0   = blockIdx.x * (2 * TA) + half * TA;

    __shared__ float ssT[2][F][TA];
    __shared__ float hhT[2][F][TA];

    #pragma unroll
    for (int t = 0; t < TA; t++) ssT[half][f][t] = g_s[(a0 + t) * F + f];
    __syncthreads();

    unsigned long long acc[TA / 2];
    {
        unsigned long long b = pk2(B1[f], B1[f]);
        #pragma unroll
        for (int p = 0; p < TA / 2; p++) acc[p] = b;
    }
    for (int g = 0; g < F; g++) {
        float w = W1[g * F + f];
        unsigned long long ww = pk2(w, w);
        const unsigned long long* row = (const unsigned long long*)&ssT[half][g][0];
        #pragma unroll
        for (int p = 0; p < TA / 2; p++) FFMA2(acc[p], row[p], ww);
    }
    #pragma unroll
    for (int p = 0; p < TA / 2; p++) {
        float2 x = upk2(acc[p]);
        hhT[half][f][2 * p]     = silu(x.x);
        hhT[half][f][2 * p + 1] = silu(x.y);
    }
    __syncthreads();

    unsigned long long p0[TA / 2], p1[TA / 2], p2[TA / 2];
    {
        unsigned long long b0 = pk2(B2[f], B2[f]);
        unsigned long long b1 = pk2(B2[F + f], B2[F + f]);
        unsigned long long b2 = pk2(B2[2 * F + f], B2[2 * F + f]);
        #pragma unroll
        for (int p = 0; p < TA / 2; p++) { p0[p] = b0; p1[p] = b1; p2[p] = b2; }
    }
    for (int g = 0; g < F; g++) {
        const float* w = W2 + g * F3;
        unsigned long long w0 = pk2(w[f], w[f]);
        unsigned long long w1 = pk2(w[F + f], w[F + f]);
        unsigned long long w2 = pk2(w[2 * F + f], w[2 * F + f]);
        const unsigned long long* row = (const unsigned long long*)&hhT[half][g][0];
        #pragma unroll
        for (int p = 0; p < TA / 2; p++) {
            FFMA2(p0[p], row[p], w0);
            FFMA2(p1[p], row[p], w1);
            FFMA2(p2[p], row[p], w2);
        }
    }
    #pragma unroll
    for (int p = 0; p < TA / 2; p++) {
        float2 x0 = upk2(p0[p]), x1 = upk2(p1[p]), x2 = upk2(p2[p]);
        int a = a0 + 2 * p;
        g_phi[a * F3 + f]               = x0.x;
        g_phi[(a + 1) * F3 + f]         = x0.y;
        g_phi[a * F3 + F + f]           = x1.x;
        g_phi[(a + 1) * F3 + F + f]     = x1.y;
        g_phi[a * F3 + 2 * F + f]       = x2.x;
        g_phi[(a + 1) * F3 + 2 * F + f] = x2.y;
    }
}

// ---------------------------------------------------------------------------
// message pass over CSR buckets (R4 structure; occupancy floor 6 blocks/SM)
// ---------------------------------------------------------------------------
__global__ void __launch_bounds__(128, 6)
k_msg(const float* __restrict__ RW, const float* __restrict__ RB,
      const int* __restrict__ nbrs)
{
    __shared__ float rw2s[NRBF * F];   // ch2 weights, 10 KB
    __shared__ int   sj  [CAP];
    __shared__ float senv[CAP];
    __shared__ float sux [CAP];
    __shared__ float suy [CAP];
    __shared__ float suz [CAP];
    __shared__ float srbf[CAP][NRBF];

    int f = threadIdx.x;

    unsigned long long rw01[NRBF];
    #pragma unroll
    for (int q = 0; q < NRBF; q++)
        rw01[q] = pk2(RW[q * F3 + f], RW[q * F3 + F + f]);
    for (int idx = f; idx < NRBF * F; idx += 128) {
        int q = idx >> 7, ff = idx & 127;
        rw2s[idx] = RW[q * F3 + 2 * F + ff];
    }
    float rb0 = RB[f], rb1 = RB[F + f], rb2 = RB[2 * F + f];

    int abase = blockIdx.x * TAM;

    for (int it = 0; it < TAM; it++) {
        int a = abase + it;
        int n = g_cnt[a];
        if (n > CAP) n = CAP;

        __syncthreads();   // prev iter smem reads done; also covers rw2s fill
        if (f < n) {
            int e = g_list[a * CAP + f];
            sj  [f] = nbrs[2 * e + 1];
            senv[f] = g_env[e];
            sux [f] = g_unit[3 * e];
            suy [f] = g_unit[3 * e + 1];
            suz [f] = g_unit[3 * e + 2];
            const float4* rp = (const float4*)(g_rbf + e * NRBF);
            float4* dst = (float4*)&srbf[f][0];
            #pragma unroll
            for (int x = 0; x < NRBF / 4; x++) dst[x] = rp[x];
        }
        __syncthreads();

        float ds = 0.0f, dv0 = 0.0f, dv1 = 0.0f, dv2 = 0.0f;
        float pj0 = 0.f, pj1 = 0.f, pj2 = 0.f, vj0 = 0.f, vj1 = 0.f, vj2 = 0.f;
        if (n > 0) {
            int j = sj[0];
            const float* pj = g_phi + j * F3;
            pj0 = pj[f]; pj1 = pj[F + f]; pj2 = pj[2 * F + f];
            const float* vj = g_v + j * F3 + f * 3;
            vj0 = vj[0]; vj1 = vj[1]; vj2 = vj[2];
        }
        for (int k = 0; k < n; k++) {
            float npj0 = 0.f, npj1 = 0.f, npj2 = 0.f, nvj0 = 0.f, nvj1 = 0.f, nvj2 = 0.f;
            if (k + 1 < n) {
                int jn = sj[k + 1];
                const float* pj = g_phi + jn * F3;
                npj0 = pj[f]; npj1 = pj[F + f]; npj2 = pj[2 * F + f];
                const float* vj = g_v + jn * F3 + f * 3;
                nvj0 = vj[0]; nvj1 = vj[1]; nvj2 = vj[2];
            }
            float env = senv[k];
            unsigned long long wA = pk2(env * rb0, env * rb1);
            unsigned long long wB = pk2(0.0f, 0.0f);
            float w2a = env * rb2, w2b = 0.0f;
            #pragma unroll
            for (int q = 0; q < NRBF; q += 2) {
                float r0 = srbf[k][q];
                float r1 = srbf[k][q + 1];
                FFMA2(wA, pk2(r0, r0), rw01[q]);
                FFMA2(wB, pk2(r1, r1), rw01[q + 1]);
                w2a = fmaf(r0, rw2s[q * F + f], w2a);
                w2b = fmaf(r1, rw2s[(q + 1) * F + f], w2b);
            }
            float2 xa = upk2(wA), xb = upk2(wB);
            float w0v = xa.x + xb.x;
            float w1v = xa.y + xb.y;
            float w2v = w2a + w2b;

            float sp0 = pj0 * w0v;
            float sp1 = pj1 * w1v;
            float sp2 = pj2 * w2v;
            ds += sp1;
            dv0 += sp2 * sux[k] + sp0 * vj0;
            dv1 += sp2 * suy[k] + sp0 * vj1;
            dv2 += sp2 * suz[k] + sp0 * vj2;

            pj0 = npj0; pj1 = npj1; pj2 = npj2;
            vj0 = nvj0; vj1 = nvj1; vj2 = nvj2;
        }
        g_ds[a * F + f] = ds;
        g_dv[a * F3 + f * 3]     = dv0;
        g_dv[a * F3 + f * 3 + 1] = dv1;
        g_dv[a * F3 + f * 3 + 2] = dv2;
    }
}

// ---------------------------------------------------------------------------
// update block (R4 structure; occupancy floor 3 blocks/SM)
// ---------------------------------------------------------------------------
__global__ void __launch_bounds__(256, 3)
k_upd(const float* __restrict__ U,  const float* __restrict__ V,
      const float* __restrict__ W1, const float* __restrict__ B1,
      const float* __restrict__ W2, const float* __restrict__ B2)
{
    int tid  = threadIdx.x;
    int half = tid >> 7;
    int f    = tid & 127;
    int a0   = blockIdx.x * (2 * TA) + half * TA;

    __shared__ float svT[2][F][3][TA];    // 24 KB
    __shared__ float stT[2][2 * F][TA];   // 16 KB (reused as shT after W1 pass)
    float (*shT)[F][TA] = (float (*)[F][TA])&stT[0][0][0];

    float snew[TA];
    #pragma unroll
    for (int t = 0; t < TA; t++) {
        int a = a0 + t;
        float s1 = g_s[a * F + f] + g_ds[a * F + f];
        snew[t]         = s1;
        stT[half][f][t] = s1;
        #pragma unroll
        for (int d = 0; d < 3; d++)
            svT[half][f][d][t] = g_v[a * F3 + f * 3 + d] + g_dv[a * F3 + f * 3 + d];
    }
    __syncthreads();

    unsigned long long ua[3][TA / 2], wa[3][TA / 2];
    #pragma unroll
    for (int d = 0; d < 3; d++)
        #pragma unroll
        for (int p = 0; p < TA / 2; p++) { ua[d][p] = 0ULL; wa[d][p] = 0ULL; }
    for (int g = 0; g < F; g++) {
        float Ug = U[g * F + f], Vg = V[g * F + f];
        unsigned long long Up = pk2(Ug, Ug), Vp = pk2(Vg, Vg);
        #pragma unroll
        for (int d = 0; d < 3; d++) {
            const unsigned long long* row = (const unsigned long long*)&svT[half][g][d][0];
            #pragma unroll
            for (int p = 0; p < TA / 2; p++) {
                unsigned long long r = row[p];
                FFMA2(ua[d][p], r, Up);
                FFMA2(wa[d][p], r, Vp);
            }
        }
    }
    float u[TA][3], uw[TA];
    #pragma unroll
    for (int p = 0; p < TA / 2; p++) {
        float wv[2][3];
        #pragma unroll
        for (int d = 0; d < 3; d++) {
            float2 xu = upk2(ua[d][p]);
            float2 xw = upk2(wa[d][p]);
            u[2 * p][d] = xu.x; u[2 * p + 1][d] = xu.y;
            wv[0][d] = xw.x;    wv[1][d] = xw.y;
        }
        #pragma unroll
        for (int h = 0; h < 2; h++) {
            int t = 2 * p + h;
            float n2 = wv[h][0] * wv[h][0] + wv[h][1] * wv[h][1] + wv[h][2] * wv[h][2];
            stT[half][F + f][t] = sqrtf(n2 + 1e-15f);
            uw[t] = u[t][0] * wv[h][0] + u[t][1] * wv[h][1] + u[t][2] * wv[h][2];
        }
    }
    __syncthreads();

    unsigned long long hacc[TA / 2];
    {
        unsigned long long b = pk2(B1[f], B1[f]);
        #pragma unroll
        for (int p = 0; p < TA / 2; p++) hacc[p] = b;
    }
    for (int r = 0; r < 2 * F; r++) {
        float wv = W1[r * F + f];
        unsigned long long ww = pk2(wv, wv);
        const unsigned long long* row = (const unsigned long long*)&stT[half][r][0];
        #pragma unroll
        for (int p = 0; p < TA / 2; p++) FFMA2(hacc[p], row[p], ww);
    }
    __syncthreads();
    #pragma unroll
    for (int p = 0; p < TA / 2; p++) {
        float2 x = upk2(hacc[p]);
        shT[half][f][2 * p]     = silu(x.x);
        shT[half][f][2 * p + 1] = silu(x.y);
    }
    __syncthreads();

    unsigned long long p0[TA / 2], p1[TA / 2], p2[TA / 2];
    {
        unsigned long long b0 = pk2(B2[f], B2[f]);
        unsigned long long b1 = pk2(B2[F + f], B2[F + f]);
        unsigned long long b2 = pk2(B2[2 * F + f], B2[2 * F + f]);
        #pragma unroll
        for (int p = 0; p < TA / 2; p++) { p0[p] = b0; p1[p] = b1; p2[p] = b2; }
    }
    for (int g = 0; g < F; g++) {
        const float* wr = W2 + g * F3;
        unsigned long long w0 = pk2(wr[f], wr[f]);
        unsigned long long w1 = pk2(wr[F + f], wr[F + f]);
        unsigned long long w2 = pk2(wr[2 * F + f], wr[2 * F + f]);
        const unsigned long long* row = (const unsigned long long*)&shT[half][g][0];
        #pragma unroll
        for (int p = 0; p < TA / 2; p++) {
            FFMA2(p0[p], row[p], w0);
            FFMA2(p1[p], row[p], w1);
            FFMA2(p2[p], row[p], w2);
        }
    }
    #pragma unroll
    for (int p = 0; p < TA / 2; p++) {
        float2 avv = upk2(p0[p]), asv = upk2(p1[p]), ass = upk2(p2[p]);
        #pragma unroll
        for (int h = 0; h < 2; h++) {
            int t = 2 * p + h;
            int a = a0 + t;
            float a_vv = h ? avv.y : avv.x;
            float a_sv = h ? asv.y : asv.x;
            float a_ss = h ? ass.y : ass.x;
            g_s[a * F + f] = snew[t] + uw[t] * a_sv + a_ss;
            #pragma unroll
            for (int d = 0; d < 3; d++)
                g_v[a * F3 + f * 3 + d] = svT[half][f][d][t] + u[t][d] * a_vv;
        }
    }
}

// ---------------------------------------------------------------------------
// readout: 16 atoms per block
// ---------------------------------------------------------------------------
#define TR 16

__global__ void k_zero_out(float* out)
{
    int t = threadIdx.x;
    if (t < NMOLS) out[t] = 0.0f;
}

__global__ void __launch_bounds__(128)
k_readout(const float* __restrict__ W1, const float* __restrict__ B1,
          const float* __restrict__ W2, const float* __restrict__ B2,
          const int* __restrict__ mol, float* __restrict__ out)
{
    int tid  = threadIdx.x;
    int half = tid >> 6;
    int t    = tid & 63;
    int ab   = blockIdx.x * TR;

    __shared__ float ssT[F][TR];
    __shared__ float red[TR][64];

    for (int x = tid; x < TR * F; x += 128) {
        int aa = x >> 7, ff = x & 127;
        ssT[ff][aa] = g_s[(ab + aa) * F + ff];
    }
    __syncthreads();

    unsigned long long acc[4];
    {
        unsigned long long b = pk2(B1[t], B1[t]);
        #pragma unroll
        for (int p = 0; p < 4; p++) acc[p] = b;
    }
    for (int g = 0; g < F; g++) {
        float w = W1[g * 64 + t];
        unsigned long long ww = pk2(w, w);
        const unsigned long long* row = (const unsigned long long*)&ssT[g][half * 8];
        #pragma unroll
        for (int p = 0; p < 4; p++) FFMA2(acc[p], row[p], ww);
    }
    float w2v = W2[t];
    #pragma unroll
    for (int p = 0; p < 4; p++) {
        float2 x = upk2(acc[p]);
        red[half * 8 + 2 * p][t]     = silu(x.x) * w2v;
        red[half * 8 + 2 * p + 1][t] = silu(x.y) * w2v;
    }
    __syncthreads();

    if (tid < TR) {
        float e = B2[0];
        #pragma unroll
        for (int q = 0; q < 64; q++) e += red[tid][q];
        atomicAdd(&out[mol[ab + tid]], e);
    }
}

// ---------------------------------------------------------------------------
// launch
// ---------------------------------------------------------------------------
extern "C" void kernel_launch(void* const* d_in, const int* in_sizes, int n_in,
                              void* d_out, int out_size)
{
    const float* xyz    = (const float*)d_in[0];
    const float* emb    = (const float*)d_in[1];
    const float* msg_w1 = (const float*)d_in[2];
    const float* msg_b1 = (const float*)d_in[3];
    const float* msg_w2 = (const float*)d_in[4];
    const float* msg_b2 = (const float*)d_in[5];
    const float* rbf_w  = (const float*)d_in[6];
    const float* rbf_b  = (const float*)d_in[7];
    const float* upd_u  = (const float*)d_in[8];
    const float* upd_v  = (const float*)d_in[9];
    const float* upd_w1 = (const float*)d_in[10];
    const float* upd_b1 = (const float*)d_in[11];
    const float* upd_w2 = (const float*)d_in[12];
    const float* upd_b2 = (const float*)d_in[13];
    const float* ro_w1  = (const float*)d_in[14];
    const float* ro_b1  = (const float*)d_in[15];
    const float* ro_w2  = (const float*)d_in[16];
    const float* ro_b2  = (const float*)d_in[17];
    const int*   z      = (const int*)d_in[18];
    const int*   nbrs   = (const int*)d_in[19];
    const int*   mol    = (const int*)d_in[20];
    float*       out    = (float*)d_out;

    int E = in_sizes[19] / 2;

    k_init <<<NATOMS, 128>>>(emb, z);
    k_edges<<<(E + 255) / 256, 256>>>(xyz, nbrs, E);

    for (int c = 0; c < NCONV; c++) {
        k_phi<<<NATOMS / (2 * TA), 256>>>(msg_w1 + c * F * F,     msg_b1 + c * F,
                                          msg_w2 + c * F * F3,    msg_b2 + c * F3);
        k_msg<<<NATOMS / TAM, 128>>>(rbf_w + c * NRBF * F3, rbf_b + c * F3, nbrs);
        k_upd<<<NATOMS / (2 * TA), 256>>>(upd_u  + c * F * F,     upd_v  + c * F * F,
                                          upd_w1 + c * 2 * F * F, upd_b1 + c * F,
                                          upd_w2 + c * F * F3,    upd_b2 + c * F3);
    }

    k_zero_out<<<1, 128>>>(out);
    k_readout <<<NATOMS / TR, 128>>>(ro_w1, ro_b1, ro_w2, ro_b2, mol, out);
}

// round 11
// speedup vs baseline: 1.2154x; 1.1255x over previous
#include <cuda_runtime.h>
#include <math.h>

// ---- problem constants ----
#define F      128
#define F3     384
#define NRBF   20
#define NATOMS 8000
#define NEDGES 160000
#define NMOLS  100
#define NCONV  3
#define CUTOFF 5.0f

#define TA  8    // atoms per half in phi/upd kernels (16 per block)
#define TAM 4    // atoms per block in msg kernel
#define CAP 64   // max active edges per destination atom

// ---- device scratch ----
__device__ float g_s   [NATOMS * F];
__device__ float g_v   [NATOMS * F3];
__device__ float g_ds  [NATOMS * F];
__device__ float g_dv  [NATOMS * F3];   // msg accumulator; reused by k_upd as u_v scratch
__device__ float g_phi [NATOMS * F3];
__device__ float g_rbf [NEDGES * NRBF];   // env-premultiplied
__device__ float g_env [NEDGES];
__device__ float g_unit[NEDGES * 3];
__device__ int   g_cnt [NATOMS];
__device__ int   g_list[NATOMS * CAP];

__device__ __forceinline__ float silu(float x) { return x / (1.0f + __expf(-x)); }

// packed fp32x2 helpers
#define FFMA2(acc, a, b) asm("fma.rn.f32x2 %0, %1, %2, %0;" : "+l"(acc) : "l"(a), "l"(b))
__device__ __forceinline__ unsigned long long pk2(float x, float y) {
    unsigned long long r; asm("mov.b64 %0, {%1, %2};" : "=l"(r) : "f"(x), "f"(y)); return r;
}
__device__ __forceinline__ float2 upk2(unsigned long long v) {
    float2 o; asm("mov.b64 {%0, %1}, %2;" : "=f"(o.x), "=f"(o.y) : "l"(v)); return o;
}

// ---------------------------------------------------------------------------
// init
// ---------------------------------------------------------------------------
__global__ void k_init(const float* __restrict__ emb, const int* __restrict__ z)
{
    int a = blockIdx.x, f = threadIdx.x;
    g_s[a * F + f] = emb[z[a] * F + f];
    int b = a * F3 + f * 3;
    g_v[b] = 0.0f; g_v[b + 1] = 0.0f; g_v[b + 2] = 0.0f;
    if (f == 0) g_cnt[a] = 0;
}

// ---------------------------------------------------------------------------
// edge geometry + CSR build
// ---------------------------------------------------------------------------
__global__ void k_edges(const float* __restrict__ xyz, const int* __restrict__ nbrs, int E)
{
    int e = blockIdx.x * 256 + threadIdx.x;
    if (e >= E) return;
    int i = nbrs[2 * e], j = nbrs[2 * e + 1];
    float rx = xyz[3 * j]     - xyz[3 * i];
    float ry = xyz[3 * j + 1] - xyz[3 * i + 1];
    float rz = xyz[3 * j + 2] - xyz[3 * i + 2];
    float d  = sqrtf(rx * rx + ry * ry + rz * rz);
    float inv = 1.0f / d;
    float t = d * (1.0f / CUTOFF);
    if (d <= CUTOFF) {
        float env = 0.5f * (cospif(t) + 1.0f);
        g_env[e] = env;
        g_unit[3 * e]     = rx * inv;
        g_unit[3 * e + 1] = ry * inv;
        g_unit[3 * e + 2] = rz * inv;
        float s = env * inv;
        #pragma unroll
        for (int k = 0; k < NRBF; k++)
            g_rbf[e * NRBF + k] = sinpif((float)(k + 1) * t) * s;
        int pos = atomicAdd(&g_cnt[i], 1);
        if (pos < CAP) g_list[i * CAP + pos] = e;
    }
}

// ---------------------------------------------------------------------------
// phi = silu(s @ W1 + b1) @ W2 + b2   (256 threads = 2 halves, 16 atoms/block)
// ---------------------------------------------------------------------------
__global__ void __launch_bounds__(256)
k_phi(const float* __restrict__ W1, const float* __restrict__ B1,
      const float* __restrict__ W2, const float* __restrict__ B2)
{
    int tid  = threadIdx.x;
    int half = tid >> 7;
    int f    = tid & 127;
    int a0   = blockIdx.x * (2 * TA) + half * TA;

    __shared__ float ssT[2][F][TA];
    __shared__ float hhT[2][F][TA];

    #pragma unroll
    for (int t = 0; t < TA; t++) ssT[half][f][t] = g_s[(a0 + t) * F + f];
    __syncthreads();

    unsigned long long acc[TA / 2];
    {
        unsigned long long b = pk2(B1[f], B1[f]);
        #pragma unroll
        for (int p = 0; p < TA / 2; p++) acc[p] = b;
    }
    for (int g = 0; g < F; g++) {
        float w = W1[g * F + f];
        unsigned long long ww = pk2(w, w);
        const unsigned long long* row = (const unsigned long long*)&ssT[half][g][0];
        #pragma unroll
        for (int p = 0; p < TA / 2; p++) FFMA2(acc[p], row[p], ww);
    }
    #pragma unroll
    for (int p = 0; p < TA / 2; p++) {
        float2 x = upk2(acc[p]);
        hhT[half][f][2 * p]     = silu(x.x);
        hhT[half][f][2 * p + 1] = silu(x.y);
    }
    __syncthreads();

    unsigned long long p0[TA / 2], p1[TA / 2], p2[TA / 2];
    {
        unsigned long long b0 = pk2(B2[f], B2[f]);
        unsigned long long b1 = pk2(B2[F + f], B2[F + f]);
        unsigned long long b2 = pk2(B2[2 * F + f], B2[2 * F + f]);
        #pragma unroll
        for (int p = 0; p < TA / 2; p++) { p0[p] = b0; p1[p] = b1; p2[p] = b2; }
    }
    for (int g = 0; g < F; g++) {
        const float* w = W2 + g * F3;
        unsigned long long w0 = pk2(w[f], w[f]);
        unsigned long long w1 = pk2(w[F + f], w[F + f]);
        unsigned long long w2 = pk2(w[2 * F + f], w[2 * F + f]);
        const unsigned long long* row = (const unsigned long long*)&hhT[half][g][0];
        #pragma unroll
        for (int p = 0; p < TA / 2; p++) {
            FFMA2(p0[p], row[p], w0);
            FFMA2(p1[p], row[p], w1);
            FFMA2(p2[p], row[p], w2);
        }
    }
    #pragma unroll
    for (int p = 0; p < TA / 2; p++) {
        float2 x0 = upk2(p0[p]), x1 = upk2(p1[p]), x2 = upk2(p2[p]);
        int a = a0 + 2 * p;
        g_phi[a * F3 + f]               = x0.x;
        g_phi[(a + 1) * F3 + f]         = x0.y;
        g_phi[a * F3 + F + f]           = x1.x;
        g_phi[(a + 1) * F3 + F + f]     = x1.y;
        g_phi[a * F3 + 2 * F + f]       = x2.x;
        g_phi[(a + 1) * F3 + 2 * F + f] = x2.y;
    }
}

// ---------------------------------------------------------------------------
// message pass over CSR buckets (R4-exact; no occupancy forcing)
// ---------------------------------------------------------------------------
__global__ void __launch_bounds__(128)
k_msg(const float* __restrict__ RW, const float* __restrict__ RB,
      const int* __restrict__ nbrs)
{
    __shared__ float rw2s[NRBF * F];   // ch2 weights, 10 KB
    __shared__ int   sj  [CAP];
    __shared__ float senv[CAP];
    __shared__ float sux [CAP];
    __shared__ float suy [CAP];
    __shared__ float suz [CAP];
    __shared__ float srbf[CAP][NRBF];

    int f = threadIdx.x;

    unsigned long long rw01[NRBF];
    #pragma unroll
    for (int q = 0; q < NRBF; q++)
        rw01[q] = pk2(RW[q * F3 + f], RW[q * F3 + F + f]);
    for (int idx = f; idx < NRBF * F; idx += 128) {
        int q = idx >> 7, ff = idx & 127;
        rw2s[idx] = RW[q * F3 + 2 * F + ff];
    }
    float rb0 = RB[f], rb1 = RB[F + f], rb2 = RB[2 * F + f];

    int abase = blockIdx.x * TAM;

    for (int it = 0; it < TAM; it++) {
        int a = abase + it;
        int n = g_cnt[a];
        if (n > CAP) n = CAP;

        __syncthreads();   // prev iter smem reads done; also covers rw2s fill
        if (f < n) {
            int e = g_list[a * CAP + f];
            sj  [f] = nbrs[2 * e + 1];
            senv[f] = g_env[e];
            sux [f] = g_unit[3 * e];
            suy [f] = g_unit[3 * e + 1];
            suz [f] = g_unit[3 * e + 2];
            const float4* rp = (const float4*)(g_rbf + e * NRBF);
            float4* dst = (float4*)&srbf[f][0];
            #pragma unroll
            for (int x = 0; x < NRBF / 4; x++) dst[x] = rp[x];
        }
        __syncthreads();

        float ds = 0.0f, dv0 = 0.0f, dv1 = 0.0f, dv2 = 0.0f;
        float pj0 = 0.f, pj1 = 0.f, pj2 = 0.f, vj0 = 0.f, vj1 = 0.f, vj2 = 0.f;
        if (n > 0) {
            int j = sj[0];
            const float* pj = g_phi + j * F3;
            pj0 = pj[f]; pj1 = pj[F + f]; pj2 = pj[2 * F + f];
            const float* vj = g_v + j * F3 + f * 3;
            vj0 = vj[0]; vj1 = vj[1]; vj2 = vj[2];
        }
        for (int k = 0; k < n; k++) {
            float npj0 = 0.f, npj1 = 0.f, npj2 = 0.f, nvj0 = 0.f, nvj1 = 0.f, nvj2 = 0.f;
            if (k + 1 < n) {
                int jn = sj[k + 1];
                const float* pj = g_phi + jn * F3;
                npj0 = pj[f]; npj1 = pj[F + f]; npj2 = pj[2 * F + f];
                const float* vj = g_v + jn * F3 + f * 3;
                nvj0 = vj[0]; nvj1 = vj[1]; nvj2 = vj[2];
            }
            float env = senv[k];
            unsigned long long wA = pk2(env * rb0, env * rb1);
            unsigned long long wB = pk2(0.0f, 0.0f);
            float w2a = env * rb2, w2b = 0.0f;
            #pragma unroll
            for (int q = 0; q < NRBF; q += 2) {
                float r0 = srbf[k][q];
                float r1 = srbf[k][q + 1];
                FFMA2(wA, pk2(r0, r0), rw01[q]);
                FFMA2(wB, pk2(r1, r1), rw01[q + 1]);
                w2a = fmaf(r0, rw2s[q * F + f], w2a);
                w2b = fmaf(r1, rw2s[(q + 1) * F + f], w2b);
            }
            float2 xa = upk2(wA), xb = upk2(wB);
            float w0v = xa.x + xb.x;
            float w1v = xa.y + xb.y;
            float w2v = w2a + w2b;

            float sp0 = pj0 * w0v;
            float sp1 = pj1 * w1v;
            float sp2 = pj2 * w2v;
            ds += sp1;
            dv0 += sp2 * sux[k] + sp0 * vj0;
            dv1 += sp2 * suy[k] + sp0 * vj1;
            dv2 += sp2 * suz[k] + sp0 * vj2;

            pj0 = npj0; pj1 = npj1; pj2 = npj2;
            vj0 = nvj0; vj1 = nvj1; vj2 = nvj2;
        }
        g_ds[a * F + f] = ds;
        g_dv[a * F3 + f * 3]     = dv0;
        g_dv[a * F3 + f * 3 + 1] = dv1;
        g_dv[a * F3 + f * 3 + 2] = dv2;
    }
}

// ---------------------------------------------------------------------------
// update block (R4 structure; u_v spilled to g_dv — dead scratch after its
// initial read — to cut ~24 registers of liveness; 3 blocks/SM floor)
// ---------------------------------------------------------------------------
__global__ void __launch_bounds__(256, 3)
k_upd(const float* __restrict__ U,  const float* __restrict__ V,
      const float* __restrict__ W1, const float* __restrict__ B1,
      const float* __restrict__ W2, const float* __restrict__ B2)
{
    int tid  = threadIdx.x;
    int half = tid >> 7;
    int f    = tid & 127;
    int a0   = blockIdx.x * (2 * TA) + half * TA;

    __shared__ float svT[2][F][3][TA];    // 24 KB
    __shared__ float stT[2][2 * F][TA];   // 16 KB (reused as shT after W1 pass)
    float (*shT)[F][TA] = (float (*)[F][TA])&stT[0][0][0];

    float snew[TA];
    #pragma unroll
    for (int t = 0; t < TA; t++) {
        int a = a0 + t;
        float s1 = g_s[a * F + f] + g_ds[a * F + f];
        snew[t]         = s1;
        stT[half][f][t] = s1;
        #pragma unroll
        for (int d = 0; d < 3; d++)
            svT[half][f][d][t] = g_v[a * F3 + f * 3 + d] + g_dv[a * F3 + f * 3 + d];
    }
    __syncthreads();

    unsigned long long ua[3][TA / 2], wa[3][TA / 2];
    #pragma unroll
    for (int d = 0; d < 3; d++)
        #pragma unroll
        for (int p = 0; p < TA / 2; p++) { ua[d][p] = 0ULL; wa[d][p] = 0ULL; }
    for (int g = 0; g < F; g++) {
        float Ug = U[g * F + f], Vg = V[g * F + f];
        unsigned long long Up = pk2(Ug, Ug), Vp = pk2(Vg, Vg);
        #pragma unroll
        for (int d = 0; d < 3; d++) {
            const unsigned long long* row = (const unsigned long long*)&svT[half][g][d][0];
            #pragma unroll
            for (int p = 0; p < TA / 2; p++) {
                unsigned long long r = row[p];
                FFMA2(ua[d][p], r, Up);
                FFMA2(wa[d][p], r, Vp);
            }
        }
    }
    // unpack: norm -> stT, uw kept in regs, u_v spilled to g_dv (dead scratch;
    // each atom's slot is touched only by the block that owns the atom)
    float uw[TA];
    #pragma unroll
    for (int p = 0; p < TA / 2; p++) {
        float uloc[2][3], wloc[2][3];
        #pragma unroll
        for (int d = 0; d < 3; d++) {
            float2 xu = upk2(ua[d][p]);
            float2 xw = upk2(wa[d][p]);
            uloc[0][d] = xu.x; uloc[1][d] = xu.y;
            wloc[0][d] = xw.x; wloc[1][d] = xw.y;
        }
        #pragma unroll
        for (int h = 0; h < 2; h++) {
            int t = 2 * p + h;
            int a = a0 + t;
            float n2 = wloc[h][0]*wloc[h][0] + wloc[h][1]*wloc[h][1] + wloc[h][2]*wloc[h][2];
            stT[half][F + f][t] = sqrtf(n2 + 1e-15f);
            uw[t] = uloc[h][0]*wloc[h][0] + uloc[h][1]*wloc[h][1] + uloc[h][2]*wloc[h][2];
            #pragma unroll
            for (int d = 0; d < 3; d++)
                g_dv[a * F3 + f * 3 + d] = uloc[h][d];
        }
    }
    __syncthreads();

    unsigned long long hacc[TA / 2];
    {
        unsigned long long b = pk2(B1[f], B1[f]);
        #pragma unroll
        for (int p = 0; p < TA / 2; p++) hacc[p] = b;
    }
    for (int r = 0; r < 2 * F; r++) {
        float wv = W1[r * F + f];
        unsigned long long ww = pk2(wv, wv);
        const unsigned long long* row = (const unsigned long long*)&stT[half][r][0];
        #pragma unroll
        for (int p = 0; p < TA / 2; p++) FFMA2(hacc[p], row[p], ww);
    }
    __syncthreads();
    #pragma unroll
    for (int p = 0; p < TA / 2; p++) {
        float2 x = upk2(hacc[p]);
        shT[half][f][2 * p]     = silu(x.x);
        shT[half][f][2 * p + 1] = silu(x.y);
    }
    __syncthreads();

    unsigned long long p0[TA / 2], p1[TA / 2], p2[TA / 2];
    {
        unsigned long long b0 = pk2(B2[f], B2[f]);
        unsigned long long b1 = pk2(B2[F + f], B2[F + f]);
        unsigned long long b2 = pk2(B2[2 * F + f], B2[2 * F + f]);
        #pragma unroll
        for (int p = 0; p < TA / 2; p++) { p0[p] = b0; p1[p] = b1; p2[p] = b2; }
    }
    for (int g = 0; g < F; g++) {
        const float* wr = W2 + g * F3;
        unsigned long long w0 = pk2(wr[f], wr[f]);
        unsigned long long w1 = pk2(wr[F + f], wr[F + f]);
        unsigned long long w2 = pk2(wr[2 * F + f], wr[2 * F + f]);
        const unsigned long long* row = (const unsigned long long*)&shT[half][g][0];
        #pragma unroll
        for (int p = 0; p < TA / 2; p++) {
            FFMA2(p0[p], row[p], w0);
            FFMA2(p1[p], row[p], w1);
            FFMA2(p2[p], row[p], w2);
        }
    }
    #pragma unroll
    for (int p = 0; p < TA / 2; p++) {
        float2 avv = upk2(p0[p]), asv = upk2(p1[p]), ass = upk2(p2[p]);
        #pragma unroll
        for (int h = 0; h < 2; h++) {
            int t = 2 * p + h;
            int a = a0 + t;
            float a_vv = h ? avv.y : avv.x;
            float a_sv = h ? asv.y : asv.x;
            float a_ss = h ? ass.y : ass.x;
            g_s[a * F + f] = snew[t] + uw[t] * a_sv + a_ss;
            #pragma unroll
            for (int d = 0; d < 3; d++) {
                int idx = a * F3 + f * 3 + d;
                g_v[idx] = svT[half][f][d][t] + g_dv[idx] * a_vv;
            }
        }
    }
}

// ---------------------------------------------------------------------------
// readout: 16 atoms per block
// ---------------------------------------------------------------------------
#define TR 16

__global__ void k_zero_out(float* out)
{
    int t = threadIdx.x;
    if (t < NMOLS) out[t] = 0.0f;
}

__global__ void __launch_bounds__(128)
k_readout(const float* __restrict__ W1, const float* __restrict__ B1,
          const float* __restrict__ W2, const float* __restrict__ B2,
          const int* __restrict__ mol, float* __restrict__ out)
{
    int tid  = threadIdx.x;
    int half = tid >> 6;
    int t    = tid & 63;
    int ab   = blockIdx.x * TR;

    __shared__ float ssT[F][TR];
    __shared__ float red[TR][64];

    for (int x = tid; x < TR * F; x += 128) {
        int aa = x >> 7, ff = x & 127;
        ssT[ff][aa] = g_s[(ab + aa) * F + ff];
    }
    __syncthreads();

    unsigned long long acc[4];
    {
        unsigned long long b = pk2(B1[t], B1[t]);
        #pragma unroll
        for (int p = 0; p < 4; p++) acc[p] = b;
    }
    for (int g = 0; g < F; g++) {
        float w = W1[g * 64 + t];
        unsigned long long ww = pk2(w, w);
        const unsigned long long* row = (const unsigned long long*)&ssT[g][half * 8];
        #pragma unroll
        for (int p = 0; p < 4; p++) FFMA2(acc[p], row[p], ww);
    }
    float w2v = W2[t];
    #pragma unroll
    for (int p = 0; p < 4; p++) {
        float2 x = upk2(acc[p]);
        red[half * 8 + 2 * p][t]     = silu(x.x) * w2v;
        red[half * 8 + 2 * p + 1][t] = silu(x.y) * w2v;
    }
    __syncthreads();

    if (tid < TR) {
        float e = B2[0];
        #pragma unroll
        for (int q = 0; q < 64; q++) e += red[tid][q];
        atomicAdd(&out[mol[ab + tid]], e);
    }
}

// ---------------------------------------------------------------------------
// launch
// ---------------------------------------------------------------------------
extern "C" void kernel_launch(void* const* d_in, const int* in_sizes, int n_in,
                              void* d_out, int out_size)
{
    const float* xyz    = (const float*)d_in[0];
    const float* emb    = (const float*)d_in[1];
    const float* msg_w1 = (const float*)d_in[2];
    const float* msg_b1 = (const float*)d_in[3];
    const float* msg_w2 = (const float*)d_in[4];
    const float* msg_b2 = (const float*)d_in[5];
    const float* rbf_w  = (const float*)d_in[6];
    const float* rbf_b  = (const float*)d_in[7];
    const float* upd_u  = (const float*)d_in[8];
    const float* upd_v  = (const float*)d_in[9];
    const float* upd_w1 = (const float*)d_in[10];
    const float* upd_b1 = (const float*)d_in[11];
    const float* upd_w2 = (const float*)d_in[12];
    const float* upd_b2 = (const float*)d_in[13];
    const float* ro_w1  = (const float*)d_in[14];
    const float* ro_b1  = (const float*)d_in[15];
    const float* ro_w2  = (const float*)d_in[16];
    const float* ro_b2  = (const float*)d_in[17];
    const int*   z      = (const int*)d_in[18];
    const int*   nbrs   = (const int*)d_in[19];
    const int*   mol    = (const int*)d_in[20];
    float*       out    = (float*)d_out;

    int E = in_sizes[19] / 2;

    k_init <<<NATOMS, 128>>>(emb, z);
    k_edges<<<(E + 255) / 256, 256>>>(xyz, nbrs, E);

    for (int c = 0; c < NCONV; c++) {
        k_phi<<<NATOMS / (2 * TA), 256>>>(msg_w1 + c * F * F,     msg_b1 + c * F,
                                          msg_w2 + c * F * F3,    msg_b2 + c * F3);
        k_msg<<<NATOMS / TAM, 128>>>(rbf_w + c * NRBF * F3, rbf_b + c * F3, nbrs);
        k_upd<<<NATOMS / (2 * TA), 256>>>(upd_u  + c * F * F,     upd_v  + c * F * F,
                                          upd_w1 + c * 2 * F * F, upd_b1 + c * F,
                                          upd_w2 + c * F * F3,    upd_b2 + c * F3);
    }

    k_zero_out<<<1, 128>>>(out);
    k_readout <<<NATOMS / TR, 128>>>(ro_w1, ro_b1, ro_w2, ro_b2, mol, out);
}

// round 12
// speedup vs baseline: 1.2785x; 1.0519x over previous
#include <cuda_runtime.h>
#include <math.h>

// ---- problem constants ----
#define F      128
#define F3     384
#define NRBF   20
#define NATOMS 8000
#define NEDGES 160000
#define NMOLS  100
#define NCONV  3
#define CUTOFF 5.0f

#define TA  8    // atoms per half in upd kernel (16 per block)
#define TAM 4    // atoms per block in msg kernel
#define CAP 64   // max active edges per destination atom
#define MT  32   // atoms per block in phi mma kernel
#define PAD 132  // padded smem row (bank-conflict-free fragment loads)

// ---- device scratch ----
__device__ float g_s   [NATOMS * F];
__device__ float g_v   [NATOMS * F3];
__device__ float g_ds  [NATOMS * F];
__device__ float g_dv  [NATOMS * F3];
__device__ float g_phi [NATOMS * F3];
__device__ float g_rbf [NEDGES * NRBF];   // env-premultiplied
__device__ float g_env [NEDGES];
__device__ float g_unit[NEDGES * 3];
__device__ int   g_cnt [NATOMS];
__device__ int   g_list[NATOMS * CAP];
// tf32 hi/lo split of msg MLP weights (all convs)
__device__ float g_w1hi[NCONV * F * F],  g_w1lo[NCONV * F * F];
__device__ float g_w2hi[NCONV * F * F3], g_w2lo[NCONV * F * F3];

__device__ __forceinline__ float silu(float x) { return x / (1.0f + __expf(-x)); }

// packed fp32x2 helpers
#define FFMA2(acc, a, b) asm("fma.rn.f32x2 %0, %1, %2, %0;" : "+l"(acc) : "l"(a), "l"(b))
__device__ __forceinline__ unsigned long long pk2(float x, float y) {
    unsigned long long r; asm("mov.b64 %0, {%1, %2};" : "=l"(r) : "f"(x), "f"(y)); return r;
}
__device__ __forceinline__ float2 upk2(unsigned long long v) {
    float2 o; asm("mov.b64 {%0, %1}, %2;" : "=f"(o.x), "=f"(o.y) : "l"(v)); return o;
}

// tf32 helpers
__device__ __forceinline__ unsigned tf32_cvt(float x) {
    unsigned r; asm("cvt.rna.tf32.f32 %0, %1;" : "=r"(r) : "f"(x)); return r;
}
__device__ __forceinline__ void tf32_split(float x, unsigned& h, unsigned& l) {
    h = tf32_cvt(x);
    l = tf32_cvt(x - __uint_as_float(h));
}
__device__ __forceinline__ void mma_tf32(float* d,
    unsigned a0, unsigned a1, unsigned a2, unsigned a3,
    unsigned b0, unsigned b1)
{
    asm("mma.sync.aligned.m16n8k8.row.col.f32.tf32.tf32.f32 "
        "{%0,%1,%2,%3}, {%4,%5,%6,%7}, {%8,%9}, {%0,%1,%2,%3};"
        : "+f"(d[0]), "+f"(d[1]), "+f"(d[2]), "+f"(d[3])
        : "r"(a0), "r"(a1), "r"(a2), "r"(a3), "r"(b0), "r"(b1));
}

// ---------------------------------------------------------------------------
// init
// ---------------------------------------------------------------------------
__global__ void k_init(const float* __restrict__ emb, const int* __restrict__ z)
{
    int a = blockIdx.x, f = threadIdx.x;
    g_s[a * F + f] = emb[z[a] * F + f];
    int b = a * F3 + f * 3;
    g_v[b] = 0.0f; g_v[b + 1] = 0.0f; g_v[b + 2] = 0.0f;
    if (f == 0) g_cnt[a] = 0;
}

// ---------------------------------------------------------------------------
// split msg MLP weights into tf32 hi/lo (run once)
// ---------------------------------------------------------------------------
__global__ void k_split(const float* __restrict__ w1, const float* __restrict__ w2)
{
    int i = blockIdx.x * 256 + threadIdx.x;
    if (i < NCONV * F * F) {
        float w = w1[i];
        unsigned h = tf32_cvt(w);
        g_w1hi[i] = __uint_as_float(h);
        g_w1lo[i] = __uint_as_float(tf32_cvt(w - __uint_as_float(h)));
    }
    if (i < NCONV * F * F3) {
        float w = w2[i];
        unsigned h = tf32_cvt(w);
        g_w2hi[i] = __uint_as_float(h);
        g_w2lo[i] = __uint_as_float(tf32_cvt(w - __uint_as_float(h)));
    }
}

// ---------------------------------------------------------------------------
// edge geometry + CSR build
// ---------------------------------------------------------------------------
__global__ void k_edges(const float* __restrict__ xyz, const int* __restrict__ nbrs, int E)
{
    int e = blockIdx.x * 256 + threadIdx.x;
    if (e >= E) return;
    int i = nbrs[2 * e], j = nbrs[2 * e + 1];
    float rx = xyz[3 * j]     - xyz[3 * i];
    float ry = xyz[3 * j + 1] - xyz[3 * i + 1];
    float rz = xyz[3 * j + 2] - xyz[3 * i + 2];
    float d  = sqrtf(rx * rx + ry * ry + rz * rz);
    float inv = 1.0f / d;
    float t = d * (1.0f / CUTOFF);
    if (d <= CUTOFF) {
        float env = 0.5f * (cospif(t) + 1.0f);
        g_env[e] = env;
        g_unit[3 * e]     = rx * inv;
        g_unit[3 * e + 1] = ry * inv;
        g_unit[3 * e + 2] = rz * inv;
        float s = env * inv;
        #pragma unroll
        for (int k = 0; k < NRBF; k++)
            g_rbf[e * NRBF + k] = sinpif((float)(k + 1) * t) * s;
        int pos = atomicAdd(&g_cnt[i], 1);
        if (pos < CAP) g_list[i * CAP + pos] = e;
    }
}

// ---------------------------------------------------------------------------
// phi via tensor cores (tf32 3x split): phi = silu(s@W1+b1)@W2+b2
// 256 threads = 8 warps; 32 atoms/block. Each warp: full M=32 (two m16
// tiles, B-fragments reused), N-slice = 16 (pass1) / 48 (pass2).
// ---------------------------------------------------------------------------
__global__ void __launch_bounds__(256)
k_phi_mma(int c, const float* __restrict__ B1, const float* __restrict__ B2)
{
    __shared__ float sA[MT][PAD];
    __shared__ float sH[MT][PAD];
    int tid  = threadIdx.x;
    int wid  = tid >> 5, lane = tid & 31;
    int gid  = lane >> 2, tg = lane & 3;
    int abase = blockIdx.x * MT;

    const float* W1hi = g_w1hi + c * F * F;
    const float* W1lo = g_w1lo + c * F * F;
    const float* W2hi = g_w2hi + c * F * F3;
    const float* W2lo = g_w2lo + c * F * F3;

    for (int x = tid; x < MT * F; x += 256)
        sA[x >> 7][x & 127] = g_s[(abase + (x >> 7)) * F + (x & 127)];
    __syncthreads();

    // ---- pass 1: H = silu(S @ W1 + b1); warp covers n in [wid*16, wid*16+16)
    {
        int nb = wid * 16;
        float acc[2][2][4];
        #pragma unroll
        for (int m = 0; m < 2; m++)
            #pragma unroll
            for (int nt = 0; nt < 2; nt++)
                #pragma unroll
                for (int q = 0; q < 4; q++) acc[m][nt][q] = 0.0f;

        for (int k0 = 0; k0 < F; k0 += 8) {
            unsigned ah[8], al[8];
            #pragma unroll
            for (int m = 0; m < 2; m++) {
                int r = m * 16 + gid;
                tf32_split(sA[r][k0 + tg],         ah[m * 4 + 0], al[m * 4 + 0]);
                tf32_split(sA[r + 8][k0 + tg],     ah[m * 4 + 1], al[m * 4 + 1]);
                tf32_split(sA[r][k0 + tg + 4],     ah[m * 4 + 2], al[m * 4 + 2]);
                tf32_split(sA[r + 8][k0 + tg + 4], ah[m * 4 + 3], al[m * 4 + 3]);
            }
            #pragma unroll
            for (int nt = 0; nt < 2; nt++) {
                int n = nb + nt * 8 + gid;
                unsigned bh0 = __float_as_uint(W1hi[(k0 + tg) * F + n]);
                unsigned bh1 = __float_as_uint(W1hi[(k0 + tg + 4) * F + n]);
                unsigned bl0 = __float_as_uint(W1lo[(k0 + tg) * F + n]);
                unsigned bl1 = __float_as_uint(W1lo[(k0 + tg + 4) * F + n]);
                #pragma unroll
                for (int m = 0; m < 2; m++) {
                    mma_tf32(acc[m][nt], ah[m*4+0], ah[m*4+1], ah[m*4+2], ah[m*4+3], bh0, bh1);
                    mma_tf32(acc[m][nt], al[m*4+0], al[m*4+1], al[m*4+2], al[m*4+3], bh0, bh1);
                    mma_tf32(acc[m][nt], ah[m*4+0], ah[m*4+1], ah[m*4+2], ah[m*4+3], bl0, bl1);
                }
            }
        }
        #pragma unroll
        for (int m = 0; m < 2; m++)
            #pragma unroll
            for (int nt = 0; nt < 2; nt++) {
                int n = nb + nt * 8 + 2 * tg;
                float b0 = B1[n], b1v = B1[n + 1];
                int r = m * 16 + gid;
                sH[r][n]         = silu(acc[m][nt][0] + b0);
                sH[r][n + 1]     = silu(acc[m][nt][1] + b1v);
                sH[r + 8][n]     = silu(acc[m][nt][2] + b0);
                sH[r + 8][n + 1] = silu(acc[m][nt][3] + b1v);
            }
    }
    __syncthreads();

    // ---- pass 2: PHI = H @ W2 + b2; warp covers n in [wid*48, wid*48+48)
    {
        int nb = wid * 48;
        float acc[2][6][4];
        #pragma unroll
        for (int m = 0; m < 2; m++)
            #pragma unroll
            for (int nt = 0; nt < 6; nt++)
                #pragma unroll
                for (int q = 0; q < 4; q++) acc[m][nt][q] = 0.0f;

        for (int k0 = 0; k0 < F; k0 += 8) {
            unsigned ah[8], al[8];
            #pragma unroll
            for (int m = 0; m < 2; m++) {
                int r = m * 16 + gid;
                tf32_split(sH[r][k0 + tg],         ah[m * 4 + 0], al[m * 4 + 0]);
                tf32_split(sH[r + 8][k0 + tg],     ah[m * 4 + 1], al[m * 4 + 1]);
                tf32_split(sH[r][k0 + tg + 4],     ah[m * 4 + 2], al[m * 4 + 2]);
                tf32_split(sH[r + 8][k0 + tg + 4], ah[m * 4 + 3], al[m * 4 + 3]);
            }
            #pragma unroll
            for (int nt = 0; nt < 6; nt++) {
                int n = nb + nt * 8 + gid;
                unsigned bh0 = __float_as_uint(W2hi[(k0 + tg) * F3 + n]);
                unsigned bh1 = __float_as_uint(W2hi[(k0 + tg + 4) * F3 + n]);
                unsigned bl0 = __float_as_uint(W2lo[(k0 + tg) * F3 + n]);
                unsigned bl1 = __float_as_uint(W2lo[(k0 + tg + 4) * F3 + n]);
                #pragma unroll
                for (int m = 0; m < 2; m++) {
                    mma_tf32(acc[m][nt], ah[m*4+0], ah[m*4+1], ah[m*4+2], ah[m*4+3], bh0, bh1);
                    mma_tf32(acc[m][nt], al[m*4+0], al[m*4+1], al[m*4+2], al[m*4+3], bh0, bh1);
                    mma_tf32(acc[m][nt], ah[m*4+0], ah[m*4+1], ah[m*4+2], ah[m*4+3], bl0, bl1);
                }
            }
        }
        #pragma unroll
        for (int m = 0; m < 2; m++)
            #pragma unroll
            for (int nt = 0; nt < 6; nt++) {
                int n = nb + nt * 8 + 2 * tg;
                float b0 = B2[n], b1v = B2[n + 1];
                int a = abase + m * 16 + gid;
                g_phi[a * F3 + n]           = acc[m][nt][0] + b0;
                g_phi[a * F3 + n + 1]       = acc[m][nt][1] + b1v;
                g_phi[(a + 8) * F3 + n]     = acc[m][nt][2] + b0;
                g_phi[(a + 8) * F3 + n + 1] = acc[m][nt][3] + b1v;
            }
    }
}

// ---------------------------------------------------------------------------
// message pass over CSR buckets (R4-exact)
// ---------------------------------------------------------------------------
__global__ void __launch_bounds__(128)
k_msg(const float* __restrict__ RW, const float* __restrict__ RB,
      const int* __restrict__ nbrs)
{
    __shared__ float rw2s[NRBF * F];   // ch2 weights, 10 KB
    __shared__ int   sj  [CAP];
    __shared__ float senv[CAP];
    __shared__ float sux [CAP];
    __shared__ float suy [CAP];
    __shared__ float suz [CAP];
    __shared__ float srbf[CAP][NRBF];

    int f = threadIdx.x;

    unsigned long long rw01[NRBF];
    #pragma unroll
    for (int q = 0; q < NRBF; q++)
        rw01[q] = pk2(RW[q * F3 + f], RW[q * F3 + F + f]);
    for (int idx = f; idx < NRBF * F; idx += 128) {
        int q = idx >> 7, ff = idx & 127;
        rw2s[idx] = RW[q * F3 + 2 * F + ff];
    }
    float rb0 = RB[f], rb1 = RB[F + f], rb2 = RB[2 * F + f];

    int abase = blockIdx.x * TAM;

    for (int it = 0; it < TAM; it++) {
        int a = abase + it;
        int n = g_cnt[a];
        if (n > CAP) n = CAP;

        __syncthreads();   // prev iter smem reads done; also covers rw2s fill
        if (f < n) {
            int e = g_list[a * CAP + f];
            sj  [f] = nbrs[2 * e + 1];
            senv[f] = g_env[e];
            sux [f] = g_unit[3 * e];
            suy [f] = g_unit[3 * e + 1];
            suz [f] = g_unit[3 * e + 2];
            const float4* rp = (const float4*)(g_rbf + e * NRBF);
            float4* dst = (float4*)&srbf[f][0];
            #pragma unroll
            for (int x = 0; x < NRBF / 4; x++) dst[x] = rp[x];
        }
        __syncthreads();

        float ds = 0.0f, dv0 = 0.0f, dv1 = 0.0f, dv2 = 0.0f;
        float pj0 = 0.f, pj1 = 0.f, pj2 = 0.f, vj0 = 0.f, vj1 = 0.f, vj2 = 0.f;
        if (n > 0) {
            int j = sj[0];
            const float* pj = g_phi + j * F3;
            pj0 = pj[f]; pj1 = pj[F + f]; pj2 = pj[2 * F + f];
            const float* vj = g_v + j * F3 + f * 3;
            vj0 = vj[0]; vj1 = vj[1]; vj2 = vj[2];
        }
        for (int k = 0; k < n; k++) {
            float npj0 = 0.f, npj1 = 0.f, npj2 = 0.f, nvj0 = 0.f, nvj1 = 0.f, nvj2 = 0.f;
            if (k + 1 < n) {
                int jn = sj[k + 1];
                const float* pj = g_phi + jn * F3;
                npj0 = pj[f]; npj1 = pj[F + f]; npj2 = pj[2 * F + f];
                const float* vj = g_v + jn * F3 + f * 3;
                nvj0 = vj[0]; nvj1 = vj[1]; nvj2 = vj[2];
            }
            float env = senv[k];
            unsigned long long wA = pk2(env * rb0, env * rb1);
            unsigned long long wB = pk2(0.0f, 0.0f);
            float w2a = env * rb2, w2b = 0.0f;
            #pragma unroll
            for (int q = 0; q < NRBF; q += 2) {
                float r0 = srbf[k][q];
                float r1 = srbf[k][q + 1];
                FFMA2(wA, pk2(r0, r0), rw01[q]);
                FFMA2(wB, pk2(r1, r1), rw01[q + 1]);
                w2a = fmaf(r0, rw2s[q * F + f], w2a);
                w2b = fmaf(r1, rw2s[(q + 1) * F + f], w2b);
            }
            float2 xa = upk2(wA), xb = upk2(wB);
            float w0v = xa.x + xb.x;
            float w1v = xa.y + xb.y;
            float w2v = w2a + w2b;

            float sp0 = pj0 * w0v;
            float sp1 = pj1 * w1v;
            float sp2 = pj2 * w2v;
            ds += sp1;
            dv0 += sp2 * sux[k] + sp0 * vj0;
            dv1 += sp2 * suy[k] + sp0 * vj1;
            dv2 += sp2 * suz[k] + sp0 * vj2;

            pj0 = npj0; pj1 = npj1; pj2 = npj2;
            vj0 = nvj0; vj1 = nvj1; vj2 = nvj2;
        }
        g_ds[a * F + f] = ds;
        g_dv[a * F3 + f * 3]     = dv0;
        g_dv[a * F3 + f * 3 + 1] = dv1;
        g_dv[a * F3 + f * 3 + 2] = dv2;
    }
}

// ---------------------------------------------------------------------------
// update block (R4-exact: 256 threads = 2 halves x 8 atoms)
// ---------------------------------------------------------------------------
__global__ void __launch_bounds__(256)
k_upd(const float* __restrict__ U,  const float* __restrict__ V,
      const float* __restrict__ W1, const float* __restrict__ B1,
      const float* __restrict__ W2, const float* __restrict__ B2)
{
    int tid  = threadIdx.x;
    int half = tid >> 7;
    int f    = tid & 127;
    int a0   = blockIdx.x * (2 * TA) + half * TA;

    __shared__ float svT[2][F][3][TA];    // 24 KB
    __shared__ float stT[2][2 * F][TA];   // 16 KB (reused as shT after W1 pass)
    float (*shT)[F][TA] = (float (*)[F][TA])&stT[0][0][0];

    float snew[TA];
    #pragma unroll
    for (int t = 0; t < TA; t++) {
        int a = a0 + t;
        float s1 = g_s[a * F + f] + g_ds[a * F + f];
        snew[t]         = s1;
        stT[half][f][t] = s1;
        #pragma unroll
        for (int d = 0; d < 3; d++)
            svT[half][f][d][t] = g_v[a * F3 + f * 3 + d] + g_dv[a * F3 + f * 3 + d];
    }
    __syncthreads();

    unsigned long long ua[3][TA / 2], wa[3][TA / 2];
    #pragma unroll
    for (int d = 0; d < 3; d++)
        #pragma unroll
        for (int p = 0; p < TA / 2; p++) { ua[d][p] = 0ULL; wa[d][p] = 0ULL; }
    for (int g = 0; g < F; g++) {
        float Ug = U[g * F + f], Vg = V[g * F + f];
        unsigned long long Up = pk2(Ug, Ug), Vp = pk2(Vg, Vg);
        #pragma unroll
        for (int d = 0; d < 3; d++) {
            const unsigned long long* row = (const unsigned long long*)&svT[half][g][d][0];
            #pragma unroll
            for (int p = 0; p < TA / 2; p++) {
                unsigned long long r = row[p];
                FFMA2(ua[d][p], r, Up);
                FFMA2(wa[d][p], r, Vp);
            }
        }
    }
    float u[TA][3], uw[TA];
    #pragma unroll
    for (int p = 0; p < TA / 2; p++) {
        float wv[2][3];
        #pragma unroll
        for (int d = 0; d < 3; d++) {
            float2 xu = upk2(ua[d][p]);
            float2 xw = upk2(wa[d][p]);
            u[2 * p][d] = xu.x; u[2 * p + 1][d] = xu.y;
            wv[0][d] = xw.x;    wv[1][d] = xw.y;
        }
        #pragma unroll
        for (int h = 0; h < 2; h++) {
            int t = 2 * p + h;
            float n2 = wv[h][0] * wv[h][0] + wv[h][1] * wv[h][1] + wv[h][2] * wv[h][2];
            stT[half][F + f][t] = sqrtf(n2 + 1e-15f);
            uw[t] = u[t][0] * wv[h][0] + u[t][1] * wv[h][1] + u[t][2] * wv[h][2];
        }
    }
    __syncthreads();

    unsigned long long hacc[TA / 2];
    {
        unsigned long long b = pk2(B1[f], B1[f]);
        #pragma unroll
        for (int p = 0; p < TA / 2; p++) hacc[p] = b;
    }
    for (int r = 0; r < 2 * F; r++) {
        float wv = W1[r * F + f];
        unsigned long long ww = pk2(wv, wv);
        const unsigned long long* row = (const unsigned long long*)&stT[half][r][0];
        #pragma unroll
        for (int p = 0; p < TA / 2; p++) FFMA2(hacc[p], row[p], ww);
    }
    __syncthreads();
    #pragma unroll
    for (int p = 0; p < TA / 2; p++) {
        float2 x = upk2(hacc[p]);
        shT[half][f][2 * p]     = silu(x.x);
        shT[half][f][2 * p + 1] = silu(x.y);
    }
    __syncthreads();

    unsigned long long p0[TA / 2], p1[TA / 2], p2[TA / 2];
    {
        unsigned long long b0 = pk2(B2[f], B2[f]);
        unsigned long long b1 = pk2(B2[F + f], B2[F + f]);
        unsigned long long b2 = pk2(B2[2 * F + f], B2[2 * F + f]);
        #pragma unroll
        for (int p = 0; p < TA / 2; p++) { p0[p] = b0; p1[p] = b1; p2[p] = b2; }
    }
    for (int g = 0; g < F; g++) {
        const float* wr = W2 + g * F3;
        unsigned long long w0 = pk2(wr[f], wr[f]);
        unsigned long long w1 = pk2(wr[F + f], wr[F + f]);
        unsigned long long w2 = pk2(wr[2 * F + f], wr[2 * F + f]);
        const unsigned long long* row = (const unsigned long long*)&shT[half][g][0];
        #pragma unroll
        for (int p = 0; p < TA / 2; p++) {
            FFMA2(p0[p], row[p], w0);
            FFMA2(p1[p], row[p], w1);
            FFMA2(p2[p], row[p], w2);
        }
    }
    #pragma unroll
    for (int p = 0; p < TA / 2; p++) {
        float2 avv = upk2(p0[p]), asv = upk2(p1[p]), ass = upk2(p2[p]);
        #pragma unroll
        for (int h = 0; h < 2; h++) {
            int t = 2 * p + h;
            int a = a0 + t;
            float a_vv = h ? avv.y : avv.x;
            float a_sv = h ? asv.y : asv.x;
            float a_ss = h ? ass.y : ass.x;
            g_s[a * F + f] = snew[t] + uw[t] * a_sv + a_ss;
            #pragma unroll
            for (int d = 0; d < 3; d++)
                g_v[a * F3 + f * 3 + d] = svT[half][f][d][t] + u[t][d] * a_vv;
        }
    }
}

// ---------------------------------------------------------------------------
// readout: 16 atoms per block
// ---------------------------------------------------------------------------
#define TR 16

__global__ void k_zero_out(float* out)
{
    int t = threadIdx.x;
    if (t < NMOLS) out[t] = 0.0f;
}

__global__ void __launch_bounds__(128)
k_readout(const float* __restrict__ W1, const float* __restrict__ B1,
          const float* __restrict__ W2, const float* __restrict__ B2,
          const int* __restrict__ mol, float* __restrict__ out)
{
    int tid  = threadIdx.x;
    int half = tid >> 6;
    int t    = tid & 63;
    int ab   = blockIdx.x * TR;

    __shared__ float ssT[F][TR];
    __shared__ float red[TR][64];

    for (int x = tid; x < TR * F; x += 128) {
        int aa = x >> 7, ff = x & 127;
        ssT[ff][aa] = g_s[(ab + aa) * F + ff];
    }
    __syncthreads();

    unsigned long long acc[4];
    {
        unsigned long long b = pk2(B1[t], B1[t]);
        #pragma unroll
        for (int p = 0; p < 4; p++) acc[p] = b;
    }
    for (int g = 0; g < F; g++) {
        float w = W1[g * 64 + t];
        unsigned long long ww = pk2(w, w);
        const unsigned long long* row = (const unsigned long long*)&ssT[g][half * 8];
        #pragma unroll
        for (int p = 0; p < 4; p++) FFMA2(acc[p], row[p], ww);
    }
    float w2v = W2[t];
    #pragma unroll
    for (int p = 0; p < 4; p++) {
        float2 x = upk2(acc[p]);
        red[half * 8 + 2 * p][t]     = silu(x.x) * w2v;
        red[half * 8 + 2 * p + 1][t] = silu(x.y) * w2v;
    }
    __syncthreads();

    if (tid < TR) {
        float e = B2[0];
        #pragma unroll
        for (int q = 0; q < 64; q++) e += red[tid][q];
        atomicAdd(&out[mol[ab + tid]], e);
    }
}

// ---------------------------------------------------------------------------
// launch
// ---------------------------------------------------------------------------
extern "C" void kernel_launch(void* const* d_in, const int* in_sizes, int n_in,
                              void* d_out, int out_size)
{
    const float* xyz    = (const float*)d_in[0];
    const float* emb    = (const float*)d_in[1];
    const float* msg_w1 = (const float*)d_in[2];
    const float* msg_b1 = (const float*)d_in[3];
    const float* msg_w2 = (const float*)d_in[4];
    const float* msg_b2 = (const float*)d_in[5];
    const float* rbf_w  = (const float*)d_in[6];
    const float* rbf_b  = (const float*)d_in[7];
    const float* upd_u  = (const float*)d_in[8];
    const float* upd_v  = (const float*)d_in[9];
    const float* upd_w1 = (const float*)d_in[10];
    const float* upd_b1 = (const float*)d_in[11];
    const float* upd_w2 = (const float*)d_in[12];
    const float* upd_b2 = (const float*)d_in[13];
    const float* ro_w1  = (const float*)d_in[14];
    const float* ro_b1  = (const float*)d_in[15];
    const float* ro_w2  = (const float*)d_in[16];
    const float* ro_b2  = (const float*)d_in[17];
    const int*   z      = (const int*)d_in[18];
    const int*   nbrs   = (const int*)d_in[19];
    const int*   mol    = (const int*)d_in[20];
    float*       out    = (float*)d_out;

    int E = in_sizes[19] / 2;

    k_init <<<NATOMS, 128>>>(emb, z);
    k_split<<<(NCONV * F * F3 + 255) / 256, 256>>>(msg_w1, msg_w2);
    k_edges<<<(E + 255) / 256, 256>>>(xyz, nbrs, E);

    for (int c = 0; c < NCONV; c++) {
        k_phi_mma<<<NATOMS / MT, 256>>>(c, msg_b1 + c * F, msg_b2 + c * F3);
        k_msg<<<NATOMS / TAM, 128>>>(rbf_w + c * NRBF * F3, rbf_b + c * F3, nbrs);
        k_upd<<<NATOMS / (2 * TA), 256>>>(upd_u  + c * F * F,     upd_v  + c * F * F,
                                          upd_w1 + c * 2 * F * F, upd_b1 + c * F,
                                          upd_w2 + c * F * F3,    upd_b2 + c * F3);
    }

    k_zero_out<<<1, 128>>>(out);
    k_readout <<<NATOMS / TR, 128>>>(ro_w1, ro_b1, ro_w2, ro_b2, mol, out);
}